// round 13
// baseline (speedup 1.0000x reference)
#include <cuda_runtime.h>
#include <cuda_fp16.h>

#define S 8192
#define E 1024
#define H 16
#define D 64
#define E3 3072

// Scratch (allocation-free rule: __device__ globals, referenced ONLY in device code)
__device__ __align__(128) __half g_Qh[H * S * D];   // pre-scaled by log2e/sqrt(D)
__device__ __align__(128) __half g_Kh[H * S * D];
__device__ __align__(128) __half g_Vh[H * S * D];
__device__ __align__(128) float  g_A[3][S * E];     // per-segment attention out (fp32)
__device__ __align__(128) __half g_xh[S * E];       // fp16 copy of x
__device__ __align__(128) __half g_wqkvh[E3 * E];   // fp16 copy of w_qkv
__device__ __align__(128) __half g_wouth[E * E];    // fp16 copy of w_out
__device__ __align__(128) __half g_Ah[S * E];       // fp16 summed attention out

// ---------------------------------------------------------------------------
// helpers
// ---------------------------------------------------------------------------
__device__ __forceinline__ unsigned packh2(float lo, float hi) {
  __half2 h = __float22half2_rn(make_float2(lo, hi));
  return *reinterpret_cast<unsigned*>(&h);
}
__device__ __forceinline__ float ex2f(float x) {
  float y; asm("ex2.approx.ftz.f32 %0, %1;" : "=f"(y) : "f"(x)); return y;
}
__device__ __forceinline__ unsigned h2ex2(unsigned x) {
  unsigned y; asm("ex2.approx.f16x2 %0, %1;" : "=r"(y) : "r"(x)); return y;
}
__device__ __forceinline__ unsigned su32(const void* p) {
  unsigned a;
  asm("{.reg .u64 t; cvta.to.shared.u64 t, %1; cvt.u32.u64 %0, t;}"
      : "=r"(a) : "l"(p));
  return a;
}
__device__ __forceinline__ void cp16(unsigned d, const void* s) {
  asm volatile("cp.async.cg.shared.global [%0], [%1], 16;" :: "r"(d), "l"(s));
}
__device__ __forceinline__ void ldsm4(unsigned& r0, unsigned& r1, unsigned& r2,
                                      unsigned& r3, unsigned a) {
  asm volatile("ldmatrix.sync.aligned.m8n8.x4.shared.b16 {%0,%1,%2,%3},[%4];"
               : "=r"(r0), "=r"(r1), "=r"(r2), "=r"(r3) : "r"(a));
}
__device__ __forceinline__ void ldsm4t(unsigned& r0, unsigned& r1, unsigned& r2,
                                       unsigned& r3, unsigned a) {
  asm volatile("ldmatrix.sync.aligned.m8n8.x4.trans.shared.b16 {%0,%1,%2,%3},[%4];"
               : "=r"(r0), "=r"(r1), "=r"(r2), "=r"(r3) : "r"(a));
}
__device__ __forceinline__ void mma16(float* d, const unsigned* a, unsigned b0,
                                      unsigned b1) {
  asm volatile(
      "mma.sync.aligned.m16n8k16.row.col.f32.f16.f16.f32 "
      "{%0,%1,%2,%3},{%4,%5,%6,%7},{%8,%9},{%0,%1,%2,%3};"
      : "+f"(d[0]), "+f"(d[1]), "+f"(d[2]), "+f"(d[3])
      : "r"(a[0]), "r"(a[1]), "r"(a[2]), "r"(a[3]), "r"(b0), "r"(b1));
}
// smem swizzle for gemm: 128B macro-rows (2 logical 64B rows)
__device__ __forceinline__ unsigned swz(int row, int c) {
  return (unsigned)((row >> 1) * 128 +
                    (((((row & 1) << 2) | c) ^ ((row >> 1) & 7)) << 4));
}

// ---------------------------------------------------------------------------
// Fused fp32 -> fp16 conversion prepass (single launch for x, w_qkv, w_out)
// ---------------------------------------------------------------------------
#define N4_X   (S * E / 4)        // 2097152
#define N4_WQ  (E3 * E / 4)       // 786432
#define N4_WO  (E * E / 4)        // 262144
__global__ void cvt_all_kernel(const float* __restrict__ x,
                               const float* __restrict__ wqkv,
                               const float* __restrict__ wout) {
  int i = blockIdx.x * blockDim.x + threadIdx.x;
  const float4* src;
  uint2* dst;
  if (i < N4_X) {
    src = (const float4*)x + i;
    dst = (uint2*)g_xh + i;
  } else if (i < N4_X + N4_WQ) {
    src = (const float4*)wqkv + (i - N4_X);
    dst = (uint2*)g_wqkvh + (i - N4_X);
  } else {
    src = (const float4*)wout + (i - N4_X - N4_WQ);
    dst = (uint2*)g_wouth + (i - N4_X - N4_WQ);
  }
  float4 v = *src;
  *dst = make_uint2(packh2(v.x, v.y), packh2(v.z, v.w));
}

// ---------------------------------------------------------------------------
// Sum segment outputs with exact coverage predicates -> fp16 A-operand.
// seg0 covers s<2048; seg1 covers s even; seg2 covers s%4==0.
// ---------------------------------------------------------------------------
__global__ void sum_a_kernel() {
  int i = blockIdx.x * blockDim.x + threadIdx.x;   // over S*E/4
  int s = i >> 8;
  float4 a = make_float4(0.f, 0.f, 0.f, 0.f);
  if (s < 2048) {
    float4 v = ((const float4*)g_A[0])[i];
    a.x += v.x; a.y += v.y; a.z += v.z; a.w += v.w;
  }
  if (!(s & 1)) {
    float4 v = ((const float4*)g_A[1])[i];
    a.x += v.x; a.y += v.y; a.z += v.z; a.w += v.w;
  }
  if (!(s & 3)) {
    float4 v = ((const float4*)g_A[2])[i];
    a.x += v.x; a.y += v.y; a.z += v.z; a.w += v.w;
  }
  ((uint2*)g_Ah)[i] = make_uint2(packh2(a.x, a.y), packh2(a.z, a.w));
}

// ---------------------------------------------------------------------------
// fp16 GEMM v5: 256x128x32 block tile, 8 warps (4x2), 64x64 warp tile,
// 1 CTA/SM (~185 regs), 3-stage cp.async pipeline (72KB dynamic smem).
// mma:ldsm = 4.0 (vs 2.67 in v2): 16 LDSM feed 64 HMMA per warp-ktile.
// mode 0: QKV scatter (fp16); mode 1: out = acc/3 + bias (fp32).
// ---------------------------------------------------------------------------
#define G5STG 3
#define G5_ABYTES 16384          // 256 rows x 64B
#define G5_BBYTES 8192           // 128 rows x 64B
#define G5B (G5_ABYTES + G5_BBYTES)
#define GEMM5_SMEM (G5STG * G5B)
__global__ __launch_bounds__(256, 1) void gemm_v5(
    const float* __restrict__ bias, float* __restrict__ Cgm, int mode) {
  extern __shared__ __align__(1024) unsigned char gsm5[];
  const unsigned smb = su32(gsm5);
  const int tid = threadIdx.x, lane = tid & 31, w = tid >> 5;
  const int wm = w >> 1, wn = w & 1;               // 4 m-warps x 2 n-warps
  const int lane7 = lane & 7, lgrp = lane >> 3;
  const int bm = blockIdx.y * 256, bn = blockIdx.x * 128;

  const __half* A = (mode == 0) ? g_xh : g_Ah;
  const __half* B = (mode == 0) ? g_wqkvh : g_wouth;

  // cp.async: A row = tid (0..255), 4 chunks; B row = tid>>1, 2 chunks
  const int browB = tid >> 1;
  const int ccB0 = (tid & 1) << 1;
  const __half* ga = A + (size_t)(bm + tid) * E;
  const __half* gb = B + (size_t)(bn + browB) * E + ccB0 * 8;
  unsigned soA[4], soB[2];
#pragma unroll
  for (int q = 0; q < 4; q++) soA[q] = swz(tid, q);
  soB[0] = swz(browB, ccB0);
  soB[1] = swz(browB, ccB0 + 1);

  auto issue = [&](int kt) {
    unsigned sa = smb + (unsigned)((kt % G5STG) * G5B);
    unsigned sb = sa + (unsigned)G5_ABYTES;
    const __half* pa = ga + kt * 32;
    const __half* pb = gb + kt * 32;
#pragma unroll
    for (int q = 0; q < 4; q++) cp16(sa + soA[q], pa + q * 8);
    cp16(sb + soB[0], pb);
    cp16(sb + soB[1], pb + 8);
    asm volatile("cp.async.commit_group;");
  };

  float acc[4][8][4];
#pragma unroll
  for (int i = 0; i < 4; i++)
#pragma unroll
    for (int j = 0; j < 8; j++)
#pragma unroll
      for (int r = 0; r < 4; r++) acc[i][j][r] = 0.f;

  const int NK = E / 32;   // 32
  issue(0);
  issue(1);

  for (int kt = 0; kt < NK; kt++) {
    if (kt < NK - 1) asm volatile("cp.async.wait_group 1;");
    else             asm volatile("cp.async.wait_group 0;");
    __syncthreads();
    if (kt + 2 < NK) issue(kt + 2);

    unsigned sa = smb + (unsigned)((kt % G5STG) * G5B);
    unsigned sb = sa + (unsigned)G5_ABYTES;
#pragma unroll
    for (int ks = 0; ks < 2; ks++) {
      unsigned af[4][4];
      const int ccA = ks * 2 + (lgrp >> 1);
#pragma unroll
      for (int ma = 0; ma < 4; ma++) {
        int row = wm * 64 + ma * 16 + ((lgrp & 1) << 3) + lane7;
        ldsm4(af[ma][0], af[ma][1], af[ma][2], af[ma][3], sa + swz(row, ccA));
      }
      unsigned bf[8][2];
      const int ccBq = ks * 2 + (lgrp & 1);
#pragma unroll
      for (int nb = 0; nb < 4; nb++) {
        int row = wn * 64 + nb * 16 + ((lgrp >> 1) << 3) + lane7;
        unsigned r0, r1, r2, r3;
        ldsm4(r0, r1, r2, r3, sb + swz(row, ccBq));
        bf[nb * 2][0] = r0;     bf[nb * 2][1] = r1;
        bf[nb * 2 + 1][0] = r2; bf[nb * 2 + 1][1] = r3;
      }
#pragma unroll
      for (int na = 0; na < 8; na++)
#pragma unroll
        for (int ma = 0; ma < 4; ma++)
          mma16(acc[ma][na], af[ma], bf[na][0], bf[na][1]);
    }
  }

  const int r = lane >> 2;
  const int cq = (lane & 3) << 1;
  if (mode == 0) {
#pragma unroll
    for (int ma = 0; ma < 4; ma++) {
      int row = bm + wm * 64 + ma * 16 + r;
#pragma unroll
      for (int na = 0; na < 8; na++) {
        int col = bn + wn * 64 + na * 8 + cq;
        int comp = col >> 10;
        int hh = (col & 1023) >> 6;
        int dd = col & 63;
        __half* base = (comp == 0) ? g_Qh : (comp == 1) ? g_Kh : g_Vh;
        float sc = (comp == 0) ? 0.125f * 1.44269504f : 1.0f;
        float2 b2 = *(const float2*)&bias[col];
        unsigned v0 = packh2((acc[ma][na][0] + b2.x) * sc,
                             (acc[ma][na][1] + b2.y) * sc);
        unsigned v1 = packh2((acc[ma][na][2] + b2.x) * sc,
                             (acc[ma][na][3] + b2.y) * sc);
        *(unsigned*)(base + (size_t)hh * S * D + (size_t)row * 64 + dd) = v0;
        *(unsigned*)(base + (size_t)hh * S * D + (size_t)(row + 8) * 64 + dd) = v1;
      }
    }
  } else {
    const float third = 1.0f / 3.0f;
#pragma unroll
    for (int ma = 0; ma < 4; ma++) {
      int row = bm + wm * 64 + ma * 16 + r;
#pragma unroll
      for (int na = 0; na < 8; na++) {
        int col = bn + wn * 64 + na * 8 + cq;
        float2 b2 = *(const float2*)&bias[col];
        float2 v0, v1;
        v0.x = fmaf(acc[ma][na][0], third, b2.x);
        v0.y = fmaf(acc[ma][na][1], third, b2.y);
        v1.x = fmaf(acc[ma][na][2], third, b2.x);
        v1.y = fmaf(acc[ma][na][3], third, b2.y);
        *(float2*)&Cgm[(size_t)row * E + col] = v0;
        *(float2*)&Cgm[(size_t)(row + 8) * E + col] = v1;
      }
    }
  }
}

// ---------------------------------------------------------------------------
// FA2 flash attention v5 (R12, verbatim): ones-column l, vote-uniform rescale
// skip, long-first CTA ordering (seg1 first).
// ---------------------------------------------------------------------------
__global__ __launch_bounds__(256, 2) void flash_fp16_v5() {
  __shared__ __align__(1024) unsigned char smem_raw[32768];
  const unsigned smb = su32(smem_raw);
  const int tid = threadIdx.x, lane = tid & 31, w = tid >> 5;
  const int lane7 = lane & 7, lgrp = lane >> 3;

  const int id = blockIdx.x;
  const int h = id & 15, qb = id >> 4;
  int qblock, n, dil, seg;
  if (qb < 32)      { seg = 1; qblock = qb;      n = 4096; dil = 2; }  // long first
  else if (qb < 48) { seg = 0; qblock = qb - 32; n = 2048; dil = 1; }
  else              { seg = 2; qblock = qb - 48; n = 2048; dil = 4; }

  const __half* Qh = g_Qh + (size_t)h * S * D;
  const __half* Kh = g_Kh + (size_t)h * S * D;
  const __half* Vh = g_Vh + (size_t)h * S * D;

  const int r0 = qblock * 128 + w * 16 + (lane >> 2);
  const int r1 = r0 + 8;
  unsigned qf[4][4];
  {
    const unsigned* q0u = (const unsigned*)(Qh + (size_t)r0 * dil * 64);
    const unsigned* q1u = (const unsigned*)(Qh + (size_t)r1 * dil * 64);
#pragma unroll
    for (int t = 0; t < 4; t++) {
      int x = t * 8 + (lane & 3);
      qf[t][0] = q0u[x];     qf[t][1] = q1u[x];
      qf[t][2] = q0u[x + 4]; qf[t][3] = q1u[x + 4];
    }
  }

  float oacc[8][4];
#pragma unroll
  for (int b = 0; b < 8; b++)
#pragma unroll
    for (int rr = 0; rr < 4; rr++) oacc[b][rr] = 0.f;
  float lacc[4] = {0.f, 0.f, 0.f, 0.f};   // l in mma accumulator (ones column)
  float m0 = -1e30f, m1 = -1e30f;

  const int krow = tid >> 2;
  const int kc0 = (tid & 3) * 2;
  const unsigned dOff0 = krow * 128 + (((kc0)     ^ (krow & 7)) << 4);
  const unsigned dOff1 = krow * 128 + (((kc0 + 1) ^ (krow & 7)) << 4);

  const unsigned rowS = (unsigned)(((lgrp >> 1) * 8 + lane7) * 128);
  unsigned cS[4];
#pragma unroll
  for (int t = 0; t < 4; t++)
    cS[t] = (unsigned)((((t * 2 + (lgrp & 1)) ^ lane7)) << 4);
  const unsigned rowV = (unsigned)((lgrp * 8 + lane7) * 128);

  const int ntiles = n >> 6;
  auto issue = [&](int kt) {
    int base = kt * 64;
    const char* ks = (const char*)(Kh + (size_t)(base + krow) * dil * 64) + kc0 * 16;
    const char* vs = (const char*)(Vh + (size_t)(base + krow) * dil * 64) + kc0 * 16;
    unsigned kb = smb + (unsigned)((kt & 1) * 8192);
    unsigned vb = smb + 16384u + (unsigned)((kt & 1) * 8192);
    cp16(kb + dOff0, ks);
    cp16(kb + dOff1, ks + 16);
    cp16(vb + dOff0, vs);
    cp16(vb + dOff1, vs + 16);
    asm volatile("cp.async.commit_group;");
  };

  const unsigned ONESH2 = 0x3C003C00u;   // half2(1.0, 1.0)

  issue(0);
  for (int kt = 0; kt < ntiles; kt++) {
    if (kt + 1 < ntiles) {
      issue(kt + 1);
      asm volatile("cp.async.wait_group 1;");
    } else {
      asm volatile("cp.async.wait_group 0;");
    }
    __syncthreads();

    const unsigned kbuf = smb + (unsigned)((kt & 1) * 8192);
    const unsigned vbuf = smb + 16384u + (unsigned)((kt & 1) * 8192);

    // S = Q K^T
    float sacc[8][4];
#pragma unroll
    for (int b = 0; b < 8; b++)
#pragma unroll
      for (int rr = 0; rr < 4; rr++) sacc[b][rr] = 0.f;
#pragma unroll
    for (int b2 = 0; b2 < 4; b2++) {
      unsigned basea = kbuf + (unsigned)(b2 * 2048) + rowS;
#pragma unroll
      for (int t = 0; t < 4; t++) {
        unsigned x0, x1, x2, x3;
        ldsm4(x0, x1, x2, x3, basea + cS[t]);
        mma16(sacc[2 * b2], qf[t], x0, x1);
        mma16(sacc[2 * b2 + 1], qf[t], x2, x3);
      }
    }

    // online softmax (log2 domain): max + P fragments only
    float mx0 = -1e30f, mx1 = -1e30f;
#pragma unroll
    for (int b = 0; b < 8; b++) {
      mx0 = fmaxf(mx0, fmaxf(sacc[b][0], sacc[b][1]));
      mx1 = fmaxf(mx1, fmaxf(sacc[b][2], sacc[b][3]));
    }
    mx0 = fmaxf(mx0, __shfl_xor_sync(0xffffffff, mx0, 1));
    mx0 = fmaxf(mx0, __shfl_xor_sync(0xffffffff, mx0, 2));
    mx1 = fmaxf(mx1, __shfl_xor_sync(0xffffffff, mx1, 1));
    mx1 = fmaxf(mx1, __shfl_xor_sync(0xffffffff, mx1, 2));
    float nm0 = fmaxf(m0, mx0), nm1 = fmaxf(m1, mx1);
    float al0 = ex2f(m0 - nm0), al1 = ex2f(m1 - nm1);
    m0 = nm0; m1 = nm1;

    unsigned pf[4][4];
#pragma unroll
    for (int b = 0; b < 8; b++) {
      pf[b >> 1][(b & 1) * 2] =
          h2ex2(packh2(sacc[b][0] - nm0, sacc[b][1] - nm0));
      pf[b >> 1][(b & 1) * 2 + 1] =
          h2ex2(packh2(sacc[b][2] - nm1, sacc[b][3] - nm1));
    }

    // vote-uniform rescale skip (no intra-warp divergence)
    if (__any_sync(0xffffffff, (al0 != 1.0f) || (al1 != 1.0f))) {
#pragma unroll
      for (int b = 0; b < 8; b++) {
        oacc[b][0] *= al0; oacc[b][1] *= al0;
        oacc[b][2] *= al1; oacc[b][3] *= al1;
      }
      lacc[0] *= al0; lacc[1] *= al0;
      lacc[2] *= al1; lacc[3] *= al1;
    }

    // l += P * ones  (all 8 output columns equal -> every lane has its row sum)
#pragma unroll
    for (int t = 0; t < 4; t++) mma16(lacc, pf[t], ONESH2, ONESH2);

    // O += P V
#pragma unroll
    for (int b = 0; b < 8; b++) {
      unsigned cv = (unsigned)(((b ^ lane7)) << 4);
      unsigned x0, x1, x2, x3, y0, y1, y2, y3;
      ldsm4t(x0, x1, x2, x3, vbuf + rowV + cv);
      ldsm4t(y0, y1, y2, y3, vbuf + rowV + 32u * 128u + cv);
      mma16(oacc[b], pf[0], x0, x1);
      mma16(oacc[b], pf[1], x2, x3);
      mma16(oacc[b], pf[2], y0, y1);
      mma16(oacc[b], pf[3], y2, y3);
    }
    __syncthreads();
  }

  const float inv0 = 1.0f / lacc[0], inv1 = 1.0f / lacc[2];
  float* base = g_A[seg];
  float* a0 = base + (size_t)r0 * dil * E + h * 64;
  float* a1 = base + (size_t)r1 * dil * E + h * 64;
#pragma unroll
  for (int b = 0; b < 8; b++) {
    int dd = b * 8 + ((lane & 3) << 1);
    *(float2*)&a0[dd] = make_float2(oacc[b][0] * inv0, oacc[b][1] * inv0);
    *(float2*)&a1[dd] = make_float2(oacc[b][2] * inv1, oacc[b][3] * inv1);
  }
}

// ---------------------------------------------------------------------------
extern "C" void kernel_launch(void* const* d_in, const int* in_sizes, int n_in,
                              void* d_out, int out_size) {
  const float* x     = (const float*)d_in[0];  // [S, E]
  const float* w_qkv = (const float*)d_in[1];  // [3E, E]
  const float* b_qkv = (const float*)d_in[2];  // [3E]
  const float* w_out = (const float*)d_in[3];  // [E, E]
  const float* b_out = (const float*)d_in[4];  // [E]
  float* out = (float*)d_out;                  // [S, E]

  static int configured = 0;
  if (!configured) {
    cudaFuncSetAttribute(gemm_v5, cudaFuncAttributeMaxDynamicSharedMemorySize,
                         GEMM5_SMEM);
    configured = 1;
  }

  // fused fp32 -> fp16 prepass (one launch)
  cvt_all_kernel<<<(N4_X + N4_WQ + N4_WO) / 256, 256>>>(x, w_qkv, w_out);

  // QKV projection (writes g_Qh/g_Kh/g_Vh)
  gemm_v5<<<dim3(E3 / 128, S / 256), 256, GEMM5_SMEM>>>(b_qkv, nullptr, 0);

  // fused flash: 64 q-blocks (32 seg1 + 16 seg0 + 16 seg2) x 16 heads
  flash_fp16_v5<<<64 * 16, 256>>>();

  // predicated per-row sum of segment slices -> fp16 A operand
  sum_a_kernel<<<(S * E / 4) / 256, 256>>>();

  // output projection
  gemm_v5<<<dim3(E / 128, S / 256), 256, GEMM5_SMEM>>>(b_out, out, 1);
}

// round 14
// speedup vs baseline: 1.1775x; 1.1775x over previous
#include <cuda_runtime.h>
#include <cuda_fp16.h>

#define S 8192
#define E 1024
#define H 16
#define D 64
#define E3 3072

// Scratch (allocation-free rule: __device__ globals, referenced ONLY in device code)
__device__ __align__(128) __half g_Qh[H * S * D];   // pre-scaled by log2e/sqrt(D)
__device__ __align__(128) __half g_Kh[H * S * D];
__device__ __align__(128) __half g_Vh[H * S * D];
__device__ __align__(128) float  g_A[3][S * E];     // per-segment attention out (fp32)
__device__ __align__(128) __half g_xh[S * E];       // fp16 copy of x
__device__ __align__(128) __half g_wqkvh[E3 * E];   // fp16 copy of w_qkv
__device__ __align__(128) __half g_wouth[E * E];    // fp16 copy of w_out
__device__ __align__(128) __half g_Ah[S * E];       // fp16 summed attention out
__device__ int g_wq;                                // flash work-queue counter

// ---------------------------------------------------------------------------
// helpers
// ---------------------------------------------------------------------------
__device__ __forceinline__ unsigned packh2(float lo, float hi) {
  __half2 h = __float22half2_rn(make_float2(lo, hi));
  return *reinterpret_cast<unsigned*>(&h);
}
__device__ __forceinline__ float ex2f(float x) {
  float y; asm("ex2.approx.ftz.f32 %0, %1;" : "=f"(y) : "f"(x)); return y;
}
__device__ __forceinline__ unsigned h2ex2(unsigned x) {
  unsigned y; asm("ex2.approx.f16x2 %0, %1;" : "=r"(y) : "r"(x)); return y;
}
__device__ __forceinline__ unsigned su32(const void* p) {
  unsigned a;
  asm("{.reg .u64 t; cvta.to.shared.u64 t, %1; cvt.u32.u64 %0, t;}"
      : "=r"(a) : "l"(p));
  return a;
}
__device__ __forceinline__ void cp16(unsigned d, const void* s) {
  asm volatile("cp.async.cg.shared.global [%0], [%1], 16;" :: "r"(d), "l"(s));
}
__device__ __forceinline__ void ldsm4(unsigned& r0, unsigned& r1, unsigned& r2,
                                      unsigned& r3, unsigned a) {
  asm volatile("ldmatrix.sync.aligned.m8n8.x4.shared.b16 {%0,%1,%2,%3},[%4];"
               : "=r"(r0), "=r"(r1), "=r"(r2), "=r"(r3) : "r"(a));
}
__device__ __forceinline__ void ldsm4t(unsigned& r0, unsigned& r1, unsigned& r2,
                                       unsigned& r3, unsigned a) {
  asm volatile("ldmatrix.sync.aligned.m8n8.x4.trans.shared.b16 {%0,%1,%2,%3},[%4];"
               : "=r"(r0), "=r"(r1), "=r"(r2), "=r"(r3) : "r"(a));
}
__device__ __forceinline__ void mma16(float* d, const unsigned* a, unsigned b0,
                                      unsigned b1) {
  asm volatile(
      "mma.sync.aligned.m16n8k16.row.col.f32.f16.f16.f32 "
      "{%0,%1,%2,%3},{%4,%5,%6,%7},{%8,%9},{%0,%1,%2,%3};"
      : "+f"(d[0]), "+f"(d[1]), "+f"(d[2]), "+f"(d[3])
      : "r"(a[0]), "r"(a[1]), "r"(a[2]), "r"(a[3]), "r"(b0), "r"(b1));
}
// smem swizzle for gemm: 128B macro-rows (2 logical 64B rows)
__device__ __forceinline__ unsigned swz(int row, int c) {
  return (unsigned)((row >> 1) * 128 +
                    (((((row & 1) << 2) | c) ^ ((row >> 1) & 7)) << 4));
}

// ---------------------------------------------------------------------------
// Fused fp32 -> fp16 conversion prepass (also resets the flash work queue)
// ---------------------------------------------------------------------------
#define N4_X   (S * E / 4)        // 2097152
#define N4_WQ  (E3 * E / 4)       // 786432
#define N4_WO  (E * E / 4)        // 262144
__global__ void cvt_all_kernel(const float* __restrict__ x,
                               const float* __restrict__ wqkv,
                               const float* __restrict__ wout) {
  int i = blockIdx.x * blockDim.x + threadIdx.x;
  if (i == 0) g_wq = 0;           // reset flash work queue (stream-ordered)
  const float4* src;
  uint2* dst;
  if (i < N4_X) {
    src = (const float4*)x + i;
    dst = (uint2*)g_xh + i;
  } else if (i < N4_X + N4_WQ) {
    src = (const float4*)wqkv + (i - N4_X);
    dst = (uint2*)g_wqkvh + (i - N4_X);
  } else {
    src = (const float4*)wout + (i - N4_X - N4_WQ);
    dst = (uint2*)g_wouth + (i - N4_X - N4_WQ);
  }
  float4 v = *src;
  *dst = make_uint2(packh2(v.x, v.y), packh2(v.z, v.w));
}

// ---------------------------------------------------------------------------
// Sum segment outputs with exact coverage predicates -> fp16 A-operand.
// seg0 covers s<2048; seg1 covers s even; seg2 covers s%4==0.
// ---------------------------------------------------------------------------
__global__ void sum_a_kernel() {
  int i = blockIdx.x * blockDim.x + threadIdx.x;   // over S*E/4
  int s = i >> 8;
  float4 a = make_float4(0.f, 0.f, 0.f, 0.f);
  if (s < 2048) {
    float4 v = ((const float4*)g_A[0])[i];
    a.x += v.x; a.y += v.y; a.z += v.z; a.w += v.w;
  }
  if (!(s & 1)) {
    float4 v = ((const float4*)g_A[1])[i];
    a.x += v.x; a.y += v.y; a.z += v.z; a.w += v.w;
  }
  if (!(s & 3)) {
    float4 v = ((const float4*)g_A[2])[i];
    a.x += v.x; a.y += v.y; a.z += v.z; a.w += v.w;
  }
  ((uint2*)g_Ah)[i] = make_uint2(packh2(a.x, a.y), packh2(a.z, a.w));
}

// ---------------------------------------------------------------------------
// fp16 GEMM v2 (R6/R12, verbatim — FROZEN): 128x128x32 tile, 256 threads,
// 3-stage cp.async + ldmatrix. mode 0: QKV scatter; mode 1: out = acc/3+bias.
// ---------------------------------------------------------------------------
#define GSTAGES 3
__global__ __launch_bounds__(256, 2) void gemm_v2(
    const float* __restrict__ bias, float* __restrict__ Cgm, int mode) {
  __shared__ __align__(1024) unsigned char smem_raw[GSTAGES * 16384];
  const unsigned smb = su32(smem_raw);
  const int tid = threadIdx.x, lane = tid & 31, w = tid >> 5;
  const int wm = w & 1, wn = w >> 1;
  const int lane7 = lane & 7, lgrp = lane >> 3;
  const int bm = blockIdx.y * 128, bn = blockIdx.x * 128;

  const __half* A = (mode == 0) ? g_xh : g_Ah;
  const __half* B = (mode == 0) ? g_wqkvh : g_wouth;

  const int crow = tid >> 1;
  const int cc0 = (tid & 1) << 1;
  const unsigned so0 = swz(crow, cc0);
  const unsigned so1 = swz(crow, cc0 + 1);
  const __half* ga = A + (size_t)(bm + crow) * E + cc0 * 8;
  const __half* gb = B + (size_t)(bn + crow) * E + cc0 * 8;

  auto issue = [&](int kt) {
    unsigned sa = smb + (unsigned)((kt % GSTAGES) * 16384);
    unsigned sb = sa + 8192u;
    const __half* pa = ga + kt * 32;
    const __half* pb = gb + kt * 32;
    cp16(sa + so0, pa);
    cp16(sa + so1, pa + 8);
    cp16(sb + so0, pb);
    cp16(sb + so1, pb + 8);
    asm volatile("cp.async.commit_group;");
  };

  float acc[4][4][4];
#pragma unroll
  for (int i = 0; i < 4; i++)
#pragma unroll
    for (int j = 0; j < 4; j++)
#pragma unroll
      for (int r = 0; r < 4; r++) acc[i][j][r] = 0.f;

  const int NK = E / 32;   // 32
  issue(0);
  issue(1);

  for (int kt = 0; kt < NK; kt++) {
    if (kt < NK - 1) asm volatile("cp.async.wait_group 1;");
    else             asm volatile("cp.async.wait_group 0;");
    __syncthreads();
    if (kt + 2 < NK) issue(kt + 2);

    unsigned sa = smb + (unsigned)((kt % GSTAGES) * 16384);
    unsigned sb = sa + 8192u;
#pragma unroll
    for (int ks = 0; ks < 2; ks++) {
      unsigned af[4][4];
      const int ccA = ks * 2 + (lgrp >> 1);
#pragma unroll
      for (int ma = 0; ma < 4; ma++) {
        int row = wm * 64 + ma * 16 + ((lgrp & 1) << 3) + lane7;
        ldsm4(af[ma][0], af[ma][1], af[ma][2], af[ma][3], sa + swz(row, ccA));
      }
      unsigned bf[4][2];
      const int ccB = ks * 2 + (lgrp & 1);
#pragma unroll
      for (int nb = 0; nb < 2; nb++) {
        int row = wn * 32 + nb * 16 + ((lgrp >> 1) << 3) + lane7;
        unsigned r0, r1, r2, r3;
        ldsm4(r0, r1, r2, r3, sb + swz(row, ccB));
        bf[nb * 2][0] = r0;     bf[nb * 2][1] = r1;
        bf[nb * 2 + 1][0] = r2; bf[nb * 2 + 1][1] = r3;
      }
#pragma unroll
      for (int na = 0; na < 4; na++)
#pragma unroll
        for (int ma = 0; ma < 4; ma++)
          mma16(acc[ma][na], af[ma], bf[na][0], bf[na][1]);
    }
  }

  const int r = lane >> 2;
  const int cq = (lane & 3) << 1;
  if (mode == 0) {
#pragma unroll
    for (int ma = 0; ma < 4; ma++) {
      int row = bm + wm * 64 + ma * 16 + r;
#pragma unroll
      for (int na = 0; na < 4; na++) {
        int col = bn + wn * 32 + na * 8 + cq;
        int comp = col >> 10;
        int hh = (col & 1023) >> 6;
        int dd = col & 63;
        __half* base = (comp == 0) ? g_Qh : (comp == 1) ? g_Kh : g_Vh;
        float sc = (comp == 0) ? 0.125f * 1.44269504f : 1.0f;
        float2 b2 = *(const float2*)&bias[col];
        unsigned v0 = packh2((acc[ma][na][0] + b2.x) * sc,
                             (acc[ma][na][1] + b2.y) * sc);
        unsigned v1 = packh2((acc[ma][na][2] + b2.x) * sc,
                             (acc[ma][na][3] + b2.y) * sc);
        *(unsigned*)(base + (size_t)hh * S * D + (size_t)row * 64 + dd) = v0;
        *(unsigned*)(base + (size_t)hh * S * D + (size_t)(row + 8) * 64 + dd) = v1;
      }
    }
  } else {
    const float third = 1.0f / 3.0f;
#pragma unroll
    for (int ma = 0; ma < 4; ma++) {
      int row = bm + wm * 64 + ma * 16 + r;
#pragma unroll
      for (int na = 0; na < 4; na++) {
        int col = bn + wn * 32 + na * 8 + cq;
        float2 b2 = *(const float2*)&bias[col];
        float2 v0, v1;
        v0.x = fmaf(acc[ma][na][0], third, b2.x);
        v0.y = fmaf(acc[ma][na][1], third, b2.y);
        v1.x = fmaf(acc[ma][na][2], third, b2.x);
        v1.y = fmaf(acc[ma][na][3], third, b2.y);
        *(float2*)&Cgm[(size_t)row * E + col] = v0;
        *(float2*)&Cgm[(size_t)(row + 8) * E + col] = v1;
      }
    }
  }
}

// ---------------------------------------------------------------------------
// FA2 flash attention v7: v5 math (ones-column l, vote-uniform rescale skip)
// in a PERSISTENT kernel with a dynamic work queue (296 CTAs, atomicAdd
// counter). Queue order = long-first (seg1 items 0..511). Output per item is
// disjoint and deterministic; only CTA->item mapping varies.
// ---------------------------------------------------------------------------
#define FLASH_CTAS 296
#define FLASH_ITEMS 1024
__global__ __launch_bounds__(256, 2) void flash_fp16_v7() {
  __shared__ __align__(1024) unsigned char smem_raw[32768];
  __shared__ int s_item;
  const unsigned smb = su32(smem_raw);
  const int tid = threadIdx.x, lane = tid & 31, w = tid >> 5;
  const int lane7 = lane & 7, lgrp = lane >> 3;

  // invariant lane geometry
  const int krow = tid >> 2;
  const int kc0 = (tid & 3) * 2;
  const unsigned dOff0 = krow * 128 + (((kc0)     ^ (krow & 7)) << 4);
  const unsigned dOff1 = krow * 128 + (((kc0 + 1) ^ (krow & 7)) << 4);
  const unsigned rowS = (unsigned)(((lgrp >> 1) * 8 + lane7) * 128);
  unsigned cS[4];
#pragma unroll
  for (int t = 0; t < 4; t++)
    cS[t] = (unsigned)((((t * 2 + (lgrp & 1)) ^ lane7)) << 4);
  const unsigned rowV = (unsigned)((lgrp * 8 + lane7) * 128);
  const unsigned ONESH2 = 0x3C003C00u;   // half2(1.0, 1.0)

  for (;;) {
    if (tid == 0) s_item = atomicAdd(&g_wq, 1);
    __syncthreads();
    const int id = s_item;
    if (id >= FLASH_ITEMS) return;

    const int h = id & 15, qb = id >> 4;
    int qblock, n, dil, seg;
    if (qb < 32)      { seg = 1; qblock = qb;      n = 4096; dil = 2; }  // long first
    else if (qb < 48) { seg = 0; qblock = qb - 32; n = 2048; dil = 1; }
    else              { seg = 2; qblock = qb - 48; n = 2048; dil = 4; }

    const __half* Qh = g_Qh + (size_t)h * S * D;
    const __half* Kh = g_Kh + (size_t)h * S * D;
    const __half* Vh = g_Vh + (size_t)h * S * D;

    const int r0 = qblock * 128 + w * 16 + (lane >> 2);
    const int r1 = r0 + 8;
    unsigned qf[4][4];
    {
      const unsigned* q0u = (const unsigned*)(Qh + (size_t)r0 * dil * 64);
      const unsigned* q1u = (const unsigned*)(Qh + (size_t)r1 * dil * 64);
#pragma unroll
      for (int t = 0; t < 4; t++) {
        int x = t * 8 + (lane & 3);
        qf[t][0] = q0u[x];     qf[t][1] = q1u[x];
        qf[t][2] = q0u[x + 4]; qf[t][3] = q1u[x + 4];
      }
    }

    float oacc[8][4];
#pragma unroll
    for (int b = 0; b < 8; b++)
#pragma unroll
      for (int rr = 0; rr < 4; rr++) oacc[b][rr] = 0.f;
    float lacc[4] = {0.f, 0.f, 0.f, 0.f};
    float m0 = -1e30f, m1 = -1e30f;

    const int ntiles = n >> 6;
    auto issue = [&](int kt) {
      int base = kt * 64;
      const char* ks = (const char*)(Kh + (size_t)(base + krow) * dil * 64) + kc0 * 16;
      const char* vs = (const char*)(Vh + (size_t)(base + krow) * dil * 64) + kc0 * 16;
      unsigned kb = smb + (unsigned)((kt & 1) * 8192);
      unsigned vb = smb + 16384u + (unsigned)((kt & 1) * 8192);
      cp16(kb + dOff0, ks);
      cp16(kb + dOff1, ks + 16);
      cp16(vb + dOff0, vs);
      cp16(vb + dOff1, vs + 16);
      asm volatile("cp.async.commit_group;");
    };

    issue(0);
    for (int kt = 0; kt < ntiles; kt++) {
      if (kt + 1 < ntiles) {
        issue(kt + 1);
        asm volatile("cp.async.wait_group 1;");
      } else {
        asm volatile("cp.async.wait_group 0;");
      }
      __syncthreads();

      const unsigned kbuf = smb + (unsigned)((kt & 1) * 8192);
      const unsigned vbuf = smb + 16384u + (unsigned)((kt & 1) * 8192);

      // S = Q K^T
      float sacc[8][4];
#pragma unroll
      for (int b = 0; b < 8; b++)
#pragma unroll
        for (int rr = 0; rr < 4; rr++) sacc[b][rr] = 0.f;
#pragma unroll
      for (int b2 = 0; b2 < 4; b2++) {
        unsigned basea = kbuf + (unsigned)(b2 * 2048) + rowS;
#pragma unroll
        for (int t = 0; t < 4; t++) {
          unsigned x0, x1, x2, x3;
          ldsm4(x0, x1, x2, x3, basea + cS[t]);
          mma16(sacc[2 * b2], qf[t], x0, x1);
          mma16(sacc[2 * b2 + 1], qf[t], x2, x3);
        }
      }

      // online softmax (log2 domain)
      float mx0 = -1e30f, mx1 = -1e30f;
#pragma unroll
      for (int b = 0; b < 8; b++) {
        mx0 = fmaxf(mx0, fmaxf(sacc[b][0], sacc[b][1]));
        mx1 = fmaxf(mx1, fmaxf(sacc[b][2], sacc[b][3]));
      }
      mx0 = fmaxf(mx0, __shfl_xor_sync(0xffffffff, mx0, 1));
      mx0 = fmaxf(mx0, __shfl_xor_sync(0xffffffff, mx0, 2));
      mx1 = fmaxf(mx1, __shfl_xor_sync(0xffffffff, mx1, 1));
      mx1 = fmaxf(mx1, __shfl_xor_sync(0xffffffff, mx1, 2));
      float nm0 = fmaxf(m0, mx0), nm1 = fmaxf(m1, mx1);
      float al0 = ex2f(m0 - nm0), al1 = ex2f(m1 - nm1);
      m0 = nm0; m1 = nm1;

      unsigned pf[4][4];
#pragma unroll
      for (int b = 0; b < 8; b++) {
        pf[b >> 1][(b & 1) * 2] =
            h2ex2(packh2(sacc[b][0] - nm0, sacc[b][1] - nm0));
        pf[b >> 1][(b & 1) * 2 + 1] =
            h2ex2(packh2(sacc[b][2] - nm1, sacc[b][3] - nm1));
      }

      if (__any_sync(0xffffffff, (al0 != 1.0f) || (al1 != 1.0f))) {
#pragma unroll
        for (int b = 0; b < 8; b++) {
          oacc[b][0] *= al0; oacc[b][1] *= al0;
          oacc[b][2] *= al1; oacc[b][3] *= al1;
        }
        lacc[0] *= al0; lacc[1] *= al0;
        lacc[2] *= al1; lacc[3] *= al1;
      }

      // l += P * ones
#pragma unroll
      for (int t = 0; t < 4; t++) mma16(lacc, pf[t], ONESH2, ONESH2);

      // O += P V
#pragma unroll
      for (int b = 0; b < 8; b++) {
        unsigned cv = (unsigned)(((b ^ lane7)) << 4);
        unsigned x0, x1, x2, x3, y0, y1, y2, y3;
        ldsm4t(x0, x1, x2, x3, vbuf + rowV + cv);
        ldsm4t(y0, y1, y2, y3, vbuf + rowV + 32u * 128u + cv);
        mma16(oacc[b], pf[0], x0, x1);
        mma16(oacc[b], pf[1], x2, x3);
        mma16(oacc[b], pf[2], y0, y1);
        mma16(oacc[b], pf[3], y2, y3);
      }
      __syncthreads();
    }

    const float inv0 = 1.0f / lacc[0], inv1 = 1.0f / lacc[2];
    float* base = g_A[seg];
    float* a0 = base + (size_t)r0 * dil * E + h * 64;
    float* a1 = base + (size_t)r1 * dil * E + h * 64;
#pragma unroll
    for (int b = 0; b < 8; b++) {
      int dd = b * 8 + ((lane & 3) << 1);
      *(float2*)&a0[dd] = make_float2(oacc[b][0] * inv0, oacc[b][1] * inv0);
      *(float2*)&a1[dd] = make_float2(oacc[b][2] * inv1, oacc[b][3] * inv1);
    }
    __syncthreads();   // all warps done with this item before s_item reuse
  }
}

// ---------------------------------------------------------------------------
extern "C" void kernel_launch(void* const* d_in, const int* in_sizes, int n_in,
                              void* d_out, int out_size) {
  const float* x     = (const float*)d_in[0];  // [S, E]
  const float* w_qkv = (const float*)d_in[1];  // [3E, E]
  const float* b_qkv = (const float*)d_in[2];  // [3E]
  const float* w_out = (const float*)d_in[3];  // [E, E]
  const float* b_out = (const float*)d_in[4];  // [E]
  float* out = (float*)d_out;                  // [S, E]

  // fused fp32 -> fp16 prepass (also resets flash work queue)
  cvt_all_kernel<<<(N4_X + N4_WQ + N4_WO) / 256, 256>>>(x, w_qkv, w_out);

  // QKV projection (writes g_Qh/g_Kh/g_Vh)
  gemm_v2<<<dim3(E3 / 128, S / 128), 256>>>(b_qkv, nullptr, 0);

  // persistent fused flash: 296 CTAs stream 1024 work items (long-first queue)
  flash_fp16_v7<<<FLASH_CTAS, 256>>>();

  // predicated per-row sum of segment slices -> fp16 A operand
  sum_a_kernel<<<(S * E / 4) / 256, 256>>>();

  // output projection
  gemm_v2<<<dim3(E / 128, S / 128), 256>>>(b_out, out, 1);
}

// round 15
// speedup vs baseline: 1.2132x; 1.0303x over previous
#include <cuda_runtime.h>
#include <cuda_fp16.h>

#define S 8192
#define E 1024
#define H 16
#define D 64
#define E3 3072
#define MC 5120   // compacted M for out-gemm: 2048 + 3072 covered upper rows

// Scratch (allocation-free rule: __device__ globals, referenced ONLY in device code)
__device__ __align__(128) __half g_Qh[H * S * D];   // pre-scaled by log2e/sqrt(D)
__device__ __align__(128) __half g_Kh[H * S * D];
__device__ __align__(128) __half g_Vh[H * S * D];
__device__ __align__(128) float  g_A[3][S * E];     // per-segment attention out (fp32)
__device__ __align__(128) __half g_xh[S * E];       // fp16 copy of x
__device__ __align__(128) __half g_wqkvh[E3 * E];   // fp16 copy of w_qkv
__device__ __align__(128) __half g_wouth[E * E];    // fp16 copy of w_out
__device__ __align__(128) __half g_Ah[S * E];       // fp16 COMPACTED attention out

// ---------------------------------------------------------------------------
// helpers
// ---------------------------------------------------------------------------
__device__ __forceinline__ unsigned packh2(float lo, float hi) {
  __half2 h = __float22half2_rn(make_float2(lo, hi));
  return *reinterpret_cast<unsigned*>(&h);
}
__device__ __forceinline__ float ex2f(float x) {
  float y; asm("ex2.approx.ftz.f32 %0, %1;" : "=f"(y) : "f"(x)); return y;
}
__device__ __forceinline__ unsigned h2ex2(unsigned x) {
  unsigned y; asm("ex2.approx.f16x2 %0, %1;" : "=r"(y) : "r"(x)); return y;
}
__device__ __forceinline__ unsigned su32(const void* p) {
  unsigned a;
  asm("{.reg .u64 t; cvta.to.shared.u64 t, %1; cvt.u32.u64 %0, t;}"
      : "=r"(a) : "l"(p));
  return a;
}
__device__ __forceinline__ void cp16(unsigned d, const void* s) {
  asm volatile("cp.async.cg.shared.global [%0], [%1], 16;" :: "r"(d), "l"(s));
}
__device__ __forceinline__ void ldsm4(unsigned& r0, unsigned& r1, unsigned& r2,
                                      unsigned& r3, unsigned a) {
  asm volatile("ldmatrix.sync.aligned.m8n8.x4.shared.b16 {%0,%1,%2,%3},[%4];"
               : "=r"(r0), "=r"(r1), "=r"(r2), "=r"(r3) : "r"(a));
}
__device__ __forceinline__ void ldsm4t(unsigned& r0, unsigned& r1, unsigned& r2,
                                       unsigned& r3, unsigned a) {
  asm volatile("ldmatrix.sync.aligned.m8n8.x4.trans.shared.b16 {%0,%1,%2,%3},[%4];"
               : "=r"(r0), "=r"(r1), "=r"(r2), "=r"(r3) : "r"(a));
}
__device__ __forceinline__ void mma16(float* d, const unsigned* a, unsigned b0,
                                      unsigned b1) {
  asm volatile(
      "mma.sync.aligned.m16n8k16.row.col.f32.f16.f16.f32 "
      "{%0,%1,%2,%3},{%4,%5,%6,%7},{%8,%9},{%0,%1,%2,%3};"
      : "+f"(d[0]), "+f"(d[1]), "+f"(d[2]), "+f"(d[3])
      : "r"(a[0]), "r"(a[1]), "r"(a[2]), "r"(a[3]), "r"(b0), "r"(b1));
}
// smem swizzle for gemm: 128B macro-rows (2 logical 64B rows)
__device__ __forceinline__ unsigned swz(int row, int c) {
  return (unsigned)((row >> 1) * 128 +
                    (((((row & 1) << 2) | c) ^ ((row >> 1) & 7)) << 4));
}

// ---------------------------------------------------------------------------
// Fused fp32 -> fp16 conversion prepass (single launch for x, w_qkv, w_out)
// ---------------------------------------------------------------------------
#define N4_X   (S * E / 4)        // 2097152
#define N4_WQ  (E3 * E / 4)       // 786432
#define N4_WO  (E * E / 4)        // 262144
__global__ void cvt_all_kernel(const float* __restrict__ x,
                               const float* __restrict__ wqkv,
                               const float* __restrict__ wout) {
  int i = blockIdx.x * blockDim.x + threadIdx.x;
  const float4* src;
  uint2* dst;
  if (i < N4_X) {
    src = (const float4*)x + i;
    dst = (uint2*)g_xh + i;
  } else if (i < N4_X + N4_WQ) {
    src = (const float4*)wqkv + (i - N4_X);
    dst = (uint2*)g_wqkvh + (i - N4_X);
  } else {
    src = (const float4*)wout + (i - N4_X - N4_WQ);
    dst = (uint2*)g_wouth + (i - N4_X - N4_WQ);
  }
  float4 v = *src;
  *dst = make_uint2(packh2(v.x, v.y), packh2(v.z, v.w));
}

// ---------------------------------------------------------------------------
// Compacted predicated sum: write only the 5120 covered rows.
// m < 2048      -> s = m        (seg0 + seg1 if even + seg2 if s%4==0)
// m in [2048,MC)-> s = 2048 + 2*(m-2048)  (always even -> seg1; seg2 if s%4==0)
// ---------------------------------------------------------------------------
__global__ void sum_a_compact_kernel() {
  int i = blockIdx.x * blockDim.x + threadIdx.x;   // over MC*E/4
  int m = i >> 8;
  int s = (m < 2048) ? m : 2048 + ((m - 2048) << 1);
  size_t off = (size_t)s * 256 + (i & 255);
  float4 a = make_float4(0.f, 0.f, 0.f, 0.f);
  if (s < 2048) {
    float4 v = ((const float4*)g_A[0])[off];
    a.x += v.x; a.y += v.y; a.z += v.z; a.w += v.w;
  }
  if (!(s & 1)) {
    float4 v = ((const float4*)g_A[1])[off];
    a.x += v.x; a.y += v.y; a.z += v.z; a.w += v.w;
  }
  if (!(s & 3)) {
    float4 v = ((const float4*)g_A[2])[off];
    a.x += v.x; a.y += v.y; a.z += v.z; a.w += v.w;
  }
  ((uint2*)g_Ah)[i] = make_uint2(packh2(a.x, a.y), packh2(a.z, a.w));
}

// ---------------------------------------------------------------------------
// Bias-only rows: odd s >= 2048 have zero attention output -> out = b_out.
// ---------------------------------------------------------------------------
__global__ void bias_fill_kernel(const float* __restrict__ bias,
                                 float* __restrict__ out) {
  int i = blockIdx.x * blockDim.x + threadIdx.x;   // over 3072*256
  int row = i >> 8;
  int e4 = i & 255;
  int s = 2049 + (row << 1);
  ((float4*)out)[(size_t)s * 256 + e4] = ((const float4*)bias)[e4];
}

// ---------------------------------------------------------------------------
// fp16 GEMM v2 (FROZEN mainloop): 128x128x32 tile, 256 threads, 3-stage
// cp.async + ldmatrix. mode 0: QKV scatter (M=8192);
// mode 1: A = g_Ah compacted (M=5120), out = acc/3 + bias scattered to s(m).
// ---------------------------------------------------------------------------
#define GSTAGES 3
__global__ __launch_bounds__(256, 2) void gemm_v2(
    const float* __restrict__ bias, float* __restrict__ Cgm, int mode) {
  __shared__ __align__(1024) unsigned char smem_raw[GSTAGES * 16384];
  const unsigned smb = su32(smem_raw);
  const int tid = threadIdx.x, lane = tid & 31, w = tid >> 5;
  const int wm = w & 1, wn = w >> 1;
  const int lane7 = lane & 7, lgrp = lane >> 3;
  const int bm = blockIdx.y * 128, bn = blockIdx.x * 128;

  const __half* A = (mode == 0) ? g_xh : g_Ah;
  const __half* B = (mode == 0) ? g_wqkvh : g_wouth;

  const int crow = tid >> 1;
  const int cc0 = (tid & 1) << 1;
  const unsigned so0 = swz(crow, cc0);
  const unsigned so1 = swz(crow, cc0 + 1);
  const __half* ga = A + (size_t)(bm + crow) * E + cc0 * 8;
  const __half* gb = B + (size_t)(bn + crow) * E + cc0 * 8;

  auto issue = [&](int kt) {
    unsigned sa = smb + (unsigned)((kt % GSTAGES) * 16384);
    unsigned sb = sa + 8192u;
    const __half* pa = ga + kt * 32;
    const __half* pb = gb + kt * 32;
    cp16(sa + so0, pa);
    cp16(sa + so1, pa + 8);
    cp16(sb + so0, pb);
    cp16(sb + so1, pb + 8);
    asm volatile("cp.async.commit_group;");
  };

  float acc[4][4][4];
#pragma unroll
  for (int i = 0; i < 4; i++)
#pragma unroll
    for (int j = 0; j < 4; j++)
#pragma unroll
      for (int r = 0; r < 4; r++) acc[i][j][r] = 0.f;

  const int NK = E / 32;   // 32
  issue(0);
  issue(1);

  for (int kt = 0; kt < NK; kt++) {
    if (kt < NK - 1) asm volatile("cp.async.wait_group 1;");
    else             asm volatile("cp.async.wait_group 0;");
    __syncthreads();
    if (kt + 2 < NK) issue(kt + 2);

    unsigned sa = smb + (unsigned)((kt % GSTAGES) * 16384);
    unsigned sb = sa + 8192u;
#pragma unroll
    for (int ks = 0; ks < 2; ks++) {
      unsigned af[4][4];
      const int ccA = ks * 2 + (lgrp >> 1);
#pragma unroll
      for (int ma = 0; ma < 4; ma++) {
        int row = wm * 64 + ma * 16 + ((lgrp & 1) << 3) + lane7;
        ldsm4(af[ma][0], af[ma][1], af[ma][2], af[ma][3], sa + swz(row, ccA));
      }
      unsigned bf[4][2];
      const int ccB = ks * 2 + (lgrp & 1);
#pragma unroll
      for (int nb = 0; nb < 2; nb++) {
        int row = wn * 32 + nb * 16 + ((lgrp >> 1) << 3) + lane7;
        unsigned r0, r1, r2, r3;
        ldsm4(r0, r1, r2, r3, sb + swz(row, ccB));
        bf[nb * 2][0] = r0;     bf[nb * 2][1] = r1;
        bf[nb * 2 + 1][0] = r2; bf[nb * 2 + 1][1] = r3;
      }
#pragma unroll
      for (int na = 0; na < 4; na++)
#pragma unroll
        for (int ma = 0; ma < 4; ma++)
          mma16(acc[ma][na], af[ma], bf[na][0], bf[na][1]);
    }
  }

  const int r = lane >> 2;
  const int cq = (lane & 3) << 1;
  if (mode == 0) {
#pragma unroll
    for (int ma = 0; ma < 4; ma++) {
      int row = bm + wm * 64 + ma * 16 + r;
#pragma unroll
      for (int na = 0; na < 4; na++) {
        int col = bn + wn * 32 + na * 8 + cq;
        int comp = col >> 10;
        int hh = (col & 1023) >> 6;
        int dd = col & 63;
        __half* base = (comp == 0) ? g_Qh : (comp == 1) ? g_Kh : g_Vh;
        float sc = (comp == 0) ? 0.125f * 1.44269504f : 1.0f;
        float2 b2 = *(const float2*)&bias[col];
        unsigned v0 = packh2((acc[ma][na][0] + b2.x) * sc,
                             (acc[ma][na][1] + b2.y) * sc);
        unsigned v1 = packh2((acc[ma][na][2] + b2.x) * sc,
                             (acc[ma][na][3] + b2.y) * sc);
        *(unsigned*)(base + (size_t)hh * S * D + (size_t)row * 64 + dd) = v0;
        *(unsigned*)(base + (size_t)hh * S * D + (size_t)(row + 8) * 64 + dd) = v1;
      }
    }
  } else {
    const float third = 1.0f / 3.0f;
#pragma unroll
    for (int ma = 0; ma < 4; ma++) {
      int row = bm + wm * 64 + ma * 16 + r;       // compacted index
      int s0 = (row < 2048) ? row : 2048 + ((row - 2048) << 1);
      int r8 = row + 8;
      int s1 = (r8 < 2048) ? r8 : 2048 + ((r8 - 2048) << 1);
#pragma unroll
      for (int na = 0; na < 4; na++) {
        int col = bn + wn * 32 + na * 8 + cq;
        float2 b2 = *(const float2*)&bias[col];
        float2 v0, v1;
        v0.x = fmaf(acc[ma][na][0], third, b2.x);
        v0.y = fmaf(acc[ma][na][1], third, b2.y);
        v1.x = fmaf(acc[ma][na][2], third, b2.x);
        v1.y = fmaf(acc[ma][na][3], third, b2.y);
        *(float2*)&Cgm[(size_t)s0 * E + col] = v0;
        *(float2*)&Cgm[(size_t)s1 * E + col] = v1;
      }
    }
  }
}

// ---------------------------------------------------------------------------
// FA2 flash attention v5 (R12, verbatim): ones-column l, vote-uniform rescale
// skip, long-first CTA ordering (seg1 first).
// ---------------------------------------------------------------------------
__global__ __launch_bounds__(256, 2) void flash_fp16_v5() {
  __shared__ __align__(1024) unsigned char smem_raw[32768];
  const unsigned smb = su32(smem_raw);
  const int tid = threadIdx.x, lane = tid & 31, w = tid >> 5;
  const int lane7 = lane & 7, lgrp = lane >> 3;

  const int id = blockIdx.x;
  const int h = id & 15, qb = id >> 4;
  int qblock, n, dil, seg;
  if (qb < 32)      { seg = 1; qblock = qb;      n = 4096; dil = 2; }  // long first
  else if (qb < 48) { seg = 0; qblock = qb - 32; n = 2048; dil = 1; }
  else              { seg = 2; qblock = qb - 48; n = 2048; dil = 4; }

  const __half* Qh = g_Qh + (size_t)h * S * D;
  const __half* Kh = g_Kh + (size_t)h * S * D;
  const __half* Vh = g_Vh + (size_t)h * S * D;

  const int r0 = qblock * 128 + w * 16 + (lane >> 2);
  const int r1 = r0 + 8;
  unsigned qf[4][4];
  {
    const unsigned* q0u = (const unsigned*)(Qh + (size_t)r0 * dil * 64);
    const unsigned* q1u = (const unsigned*)(Qh + (size_t)r1 * dil * 64);
#pragma unroll
    for (int t = 0; t < 4; t++) {
      int x = t * 8 + (lane & 3);
      qf[t][0] = q0u[x];     qf[t][1] = q1u[x];
      qf[t][2] = q0u[x + 4]; qf[t][3] = q1u[x + 4];
    }
  }

  float oacc[8][4];
#pragma unroll
  for (int b = 0; b < 8; b++)
#pragma unroll
    for (int rr = 0; rr < 4; rr++) oacc[b][rr] = 0.f;
  float lacc[4] = {0.f, 0.f, 0.f, 0.f};   // l in mma accumulator (ones column)
  float m0 = -1e30f, m1 = -1e30f;

  const int krow = tid >> 2;
  const int kc0 = (tid & 3) * 2;
  const unsigned dOff0 = krow * 128 + (((kc0)     ^ (krow & 7)) << 4);
  const unsigned dOff1 = krow * 128 + (((kc0 + 1) ^ (krow & 7)) << 4);

  const unsigned rowS = (unsigned)(((lgrp >> 1) * 8 + lane7) * 128);
  unsigned cS[4];
#pragma unroll
  for (int t = 0; t < 4; t++)
    cS[t] = (unsigned)((((t * 2 + (lgrp & 1)) ^ lane7)) << 4);
  const unsigned rowV = (unsigned)((lgrp * 8 + lane7) * 128);

  const int ntiles = n >> 6;
  auto issue = [&](int kt) {
    int base = kt * 64;
    const char* ks = (const char*)(Kh + (size_t)(base + krow) * dil * 64) + kc0 * 16;
    const char* vs = (const char*)(Vh + (size_t)(base + krow) * dil * 64) + kc0 * 16;
    unsigned kb = smb + (unsigned)((kt & 1) * 8192);
    unsigned vb = smb + 16384u + (unsigned)((kt & 1) * 8192);
    cp16(kb + dOff0, ks);
    cp16(kb + dOff1, ks + 16);
    cp16(vb + dOff0, vs);
    cp16(vb + dOff1, vs + 16);
    asm volatile("cp.async.commit_group;");
  };

  const unsigned ONESH2 = 0x3C003C00u;   // half2(1.0, 1.0)

  issue(0);
  for (int kt = 0; kt < ntiles; kt++) {
    if (kt + 1 < ntiles) {
      issue(kt + 1);
      asm volatile("cp.async.wait_group 1;");
    } else {
      asm volatile("cp.async.wait_group 0;");
    }
    __syncthreads();

    const unsigned kbuf = smb + (unsigned)((kt & 1) * 8192);
    const unsigned vbuf = smb + 16384u + (unsigned)((kt & 1) * 8192);

    // S = Q K^T
    float sacc[8][4];
#pragma unroll
    for (int b = 0; b < 8; b++)
#pragma unroll
      for (int rr = 0; rr < 4; rr++) sacc[b][rr] = 0.f;
#pragma unroll
    for (int b2 = 0; b2 < 4; b2++) {
      unsigned basea = kbuf + (unsigned)(b2 * 2048) + rowS;
#pragma unroll
      for (int t = 0; t < 4; t++) {
        unsigned x0, x1, x2, x3;
        ldsm4(x0, x1, x2, x3, basea + cS[t]);
        mma16(sacc[2 * b2], qf[t], x0, x1);
        mma16(sacc[2 * b2 + 1], qf[t], x2, x3);
      }
    }

    // online softmax (log2 domain): max + P fragments only
    float mx0 = -1e30f, mx1 = -1e30f;
#pragma unroll
    for (int b = 0; b < 8; b++) {
      mx0 = fmaxf(mx0, fmaxf(sacc[b][0], sacc[b][1]));
      mx1 = fmaxf(mx1, fmaxf(sacc[b][2], sacc[b][3]));
    }
    mx0 = fmaxf(mx0, __shfl_xor_sync(0xffffffff, mx0, 1));
    mx0 = fmaxf(mx0, __shfl_xor_sync(0xffffffff, mx0, 2));
    mx1 = fmaxf(mx1, __shfl_xor_sync(0xffffffff, mx1, 1));
    mx1 = fmaxf(mx1, __shfl_xor_sync(0xffffffff, mx1, 2));
    float nm0 = fmaxf(m0, mx0), nm1 = fmaxf(m1, mx1);
    float al0 = ex2f(m0 - nm0), al1 = ex2f(m1 - nm1);
    m0 = nm0; m1 = nm1;

    unsigned pf[4][4];
#pragma unroll
    for (int b = 0; b < 8; b++) {
      pf[b >> 1][(b & 1) * 2] =
          h2ex2(packh2(sacc[b][0] - nm0, sacc[b][1] - nm0));
      pf[b >> 1][(b & 1) * 2 + 1] =
          h2ex2(packh2(sacc[b][2] - nm1, sacc[b][3] - nm1));
    }

    // vote-uniform rescale skip (no intra-warp divergence)
    if (__any_sync(0xffffffff, (al0 != 1.0f) || (al1 != 1.0f))) {
#pragma unroll
      for (int b = 0; b < 8; b++) {
        oacc[b][0] *= al0; oacc[b][1] *= al0;
        oacc[b][2] *= al1; oacc[b][3] *= al1;
      }
      lacc[0] *= al0; lacc[1] *= al0;
      lacc[2] *= al1; lacc[3] *= al1;
    }

    // l += P * ones  (all 8 output columns equal -> every lane has its row sum)
#pragma unroll
    for (int t = 0; t < 4; t++) mma16(lacc, pf[t], ONESH2, ONESH2);

    // O += P V
#pragma unroll
    for (int b = 0; b < 8; b++) {
      unsigned cv = (unsigned)(((b ^ lane7)) << 4);
      unsigned x0, x1, x2, x3, y0, y1, y2, y3;
      ldsm4t(x0, x1, x2, x3, vbuf + rowV + cv);
      ldsm4t(y0, y1, y2, y3, vbuf + rowV + 32u * 128u + cv);
      mma16(oacc[b], pf[0], x0, x1);
      mma16(oacc[b], pf[1], x2, x3);
      mma16(oacc[b], pf[2], y0, y1);
      mma16(oacc[b], pf[3], y2, y3);
    }
    __syncthreads();
  }

  const float inv0 = 1.0f / lacc[0], inv1 = 1.0f / lacc[2];
  float* base = g_A[seg];
  float* a0 = base + (size_t)r0 * dil * E + h * 64;
  float* a1 = base + (size_t)r1 * dil * E + h * 64;
#pragma unroll
  for (int b = 0; b < 8; b++) {
    int dd = b * 8 + ((lane & 3) << 1);
    *(float2*)&a0[dd] = make_float2(oacc[b][0] * inv0, oacc[b][1] * inv0);
    *(float2*)&a1[dd] = make_float2(oacc[b][2] * inv1, oacc[b][3] * inv1);
  }
}

// ---------------------------------------------------------------------------
extern "C" void kernel_launch(void* const* d_in, const int* in_sizes, int n_in,
                              void* d_out, int out_size) {
  const float* x     = (const float*)d_in[0];  // [S, E]
  const float* w_qkv = (const float*)d_in[1];  // [3E, E]
  const float* b_qkv = (const float*)d_in[2];  // [3E]
  const float* w_out = (const float*)d_in[3];  // [E, E]
  const float* b_out = (const float*)d_in[4];  // [E]
  float* out = (float*)d_out;                  // [S, E]

  // fused fp32 -> fp16 prepass (one launch)
  cvt_all_kernel<<<(N4_X + N4_WQ + N4_WO) / 256, 256>>>(x, w_qkv, w_out);

  // QKV projection (writes g_Qh/g_Kh/g_Vh)
  gemm_v2<<<dim3(E3 / 128, S / 128), 256>>>(b_qkv, nullptr, 0);

  // fused flash: 64 q-blocks (32 seg1 + 16 seg0 + 16 seg2) x 16 heads
  flash_fp16_v5<<<64 * 16, 256>>>();

  // bias-only rows (odd s >= 2048): out = b_out
  bias_fill_kernel<<<(3072 * 256) / 256, 256>>>(b_out, out);

  // compacted predicated sum -> fp16 A operand (M = 5120)
  sum_a_compact_kernel<<<(MC * E / 4) / 256, 256>>>();

  // output projection over compacted rows, epilogue scatters to s(m)
  gemm_v2<<<dim3(E / 128, MC / 128), 256>>>(b_out, out, 1);
}

// round 16
// speedup vs baseline: 1.3572x; 1.1188x over previous
#include <cuda_runtime.h>
#include <cuda_fp16.h>

#define S 8192
#define E 1024
#define H 16
#define D 64
#define E3 3072
#define MC 5120   // compacted M: 2048 + 3072 covered upper rows (even s >= 2048)

// Scratch (allocation-free rule: __device__ globals, referenced ONLY in device code)
__device__ __align__(128) __half g_Qh[H * S * D];   // pre-scaled by log2e/sqrt(D)
__device__ __align__(128) __half g_Kh[H * S * D];
__device__ __align__(128) __half g_Vh[H * S * D];
__device__ __align__(128) float  g_A[3][S * E];     // per-segment attention out (fp32)
__device__ __align__(128) __half g_xh[S * E];       // fp16 copy of x
__device__ __align__(128) __half g_wqkvh[E3 * E];   // fp16 copy of w_qkv
__device__ __align__(128) __half g_wouth[E * E];    // fp16 copy of w_out
__device__ __align__(128) __half g_Ah[S * E];       // fp16 COMPACTED attention out

// ---------------------------------------------------------------------------
// helpers
// ---------------------------------------------------------------------------
__device__ __forceinline__ unsigned packh2(float lo, float hi) {
  __half2 h = __float22half2_rn(make_float2(lo, hi));
  return *reinterpret_cast<unsigned*>(&h);
}
__device__ __forceinline__ float ex2f(float x) {
  float y; asm("ex2.approx.ftz.f32 %0, %1;" : "=f"(y) : "f"(x)); return y;
}
__device__ __forceinline__ unsigned h2ex2(unsigned x) {
  unsigned y; asm("ex2.approx.f16x2 %0, %1;" : "=r"(y) : "r"(x)); return y;
}
__device__ __forceinline__ unsigned su32(const void* p) {
  unsigned a;
  asm("{.reg .u64 t; cvta.to.shared.u64 t, %1; cvt.u32.u64 %0, t;}"
      : "=r"(a) : "l"(p));
  return a;
}
__device__ __forceinline__ void cp16(unsigned d, const void* s) {
  asm volatile("cp.async.cg.shared.global [%0], [%1], 16;" :: "r"(d), "l"(s));
}
__device__ __forceinline__ void ldsm4(unsigned& r0, unsigned& r1, unsigned& r2,
                                      unsigned& r3, unsigned a) {
  asm volatile("ldmatrix.sync.aligned.m8n8.x4.shared.b16 {%0,%1,%2,%3},[%4];"
               : "=r"(r0), "=r"(r1), "=r"(r2), "=r"(r3) : "r"(a));
}
__device__ __forceinline__ void ldsm4t(unsigned& r0, unsigned& r1, unsigned& r2,
                                       unsigned& r3, unsigned a) {
  asm volatile("ldmatrix.sync.aligned.m8n8.x4.trans.shared.b16 {%0,%1,%2,%3},[%4];"
               : "=r"(r0), "=r"(r1), "=r"(r2), "=r"(r3) : "r"(a));
}
__device__ __forceinline__ void mma16(float* d, const unsigned* a, unsigned b0,
                                      unsigned b1) {
  asm volatile(
      "mma.sync.aligned.m16n8k16.row.col.f32.f16.f16.f32 "
      "{%0,%1,%2,%3},{%4,%5,%6,%7},{%8,%9},{%0,%1,%2,%3};"
      : "+f"(d[0]), "+f"(d[1]), "+f"(d[2]), "+f"(d[3])
      : "r"(a[0]), "r"(a[1]), "r"(a[2]), "r"(a[3]), "r"(b0), "r"(b1));
}
// smem swizzle for gemm: 128B macro-rows (2 logical 64B rows)
__device__ __forceinline__ unsigned swz(int row, int c) {
  return (unsigned)((row >> 1) * 128 +
                    (((((row & 1) << 2) | c) ^ ((row >> 1) & 7)) << 4));
}
// compacted index -> original sequence position
__device__ __forceinline__ int cmap(int m) {
  return (m < 2048) ? m : 2048 + ((m - 2048) << 1);
}

// ---------------------------------------------------------------------------
// Fused fp32 -> fp16 conversion prepass (single launch for x, w_qkv, w_out)
// ---------------------------------------------------------------------------
#define N4_X   (S * E / 4)        // 2097152
#define N4_WQ  (E3 * E / 4)       // 786432
#define N4_WO  (E * E / 4)        // 262144
__global__ void cvt_all_kernel(const float* __restrict__ x,
                               const float* __restrict__ wqkv,
                               const float* __restrict__ wout) {
  int i = blockIdx.x * blockDim.x + threadIdx.x;
  const float4* src;
  uint2* dst;
  if (i < N4_X) {
    src = (const float4*)x + i;
    dst = (uint2*)g_xh + i;
  } else if (i < N4_X + N4_WQ) {
    src = (const float4*)wqkv + (i - N4_X);
    dst = (uint2*)g_wqkvh + (i - N4_X);
  } else {
    src = (const float4*)wout + (i - N4_X - N4_WQ);
    dst = (uint2*)g_wouth + (i - N4_X - N4_WQ);
  }
  float4 v = *src;
  *dst = make_uint2(packh2(v.x, v.y), packh2(v.z, v.w));
}

// ---------------------------------------------------------------------------
// Compacted predicated sum: write only the 5120 covered rows.
// ---------------------------------------------------------------------------
__global__ void sum_a_compact_kernel() {
  int i = blockIdx.x * blockDim.x + threadIdx.x;   // over MC*E/4
  int m = i >> 8;
  int s = cmap(m);
  size_t off = (size_t)s * 256 + (i & 255);
  float4 a = make_float4(0.f, 0.f, 0.f, 0.f);
  if (s < 2048) {
    float4 v = ((const float4*)g_A[0])[off];
    a.x += v.x; a.y += v.y; a.z += v.z; a.w += v.w;
  }
  if (!(s & 1)) {
    float4 v = ((const float4*)g_A[1])[off];
    a.x += v.x; a.y += v.y; a.z += v.z; a.w += v.w;
  }
  if (!(s & 3)) {
    float4 v = ((const float4*)g_A[2])[off];
    a.x += v.x; a.y += v.y; a.z += v.z; a.w += v.w;
  }
  ((uint2*)g_Ah)[i] = make_uint2(packh2(a.x, a.y), packh2(a.z, a.w));
}

// ---------------------------------------------------------------------------
// Bias-only rows: odd s >= 2048 have zero attention output -> out = b_out.
// ---------------------------------------------------------------------------
__global__ void bias_fill_kernel(const float* __restrict__ bias,
                                 float* __restrict__ out) {
  int i = blockIdx.x * blockDim.x + threadIdx.x;   // over 3072*256
  int row = i >> 8;
  int e4 = i & 255;
  int s = 2049 + (row << 1);
  ((float4*)out)[(size_t)s * 256 + e4] = ((const float4*)bias)[e4];
}

// ---------------------------------------------------------------------------
// fp16 GEMM v2 (FROZEN mainloop): 128x128x32 tile, 256 threads, 3-stage
// cp.async + ldmatrix. Both modes run over COMPACTED M = 5120:
// mode 0: A = g_xh gathered at s(m), scatter Q/K/V to ORIGINAL rows s(m)
//         (flash reads original positions; uncovered rows never read).
// mode 1: A = g_Ah compacted (linear), out = acc/3 + bias scattered to s(m).
// ---------------------------------------------------------------------------
#define GSTAGES 3
__global__ __launch_bounds__(256, 2) void gemm_v2(
    const float* __restrict__ bias, float* __restrict__ Cgm, int mode) {
  __shared__ __align__(1024) unsigned char smem_raw[GSTAGES * 16384];
  const unsigned smb = su32(smem_raw);
  const int tid = threadIdx.x, lane = tid & 31, w = tid >> 5;
  const int wm = w & 1, wn = w >> 1;
  const int lane7 = lane & 7, lgrp = lane >> 3;
  const int bm = blockIdx.y * 128, bn = blockIdx.x * 128;

  const __half* A = (mode == 0) ? g_xh : g_Ah;
  const __half* B = (mode == 0) ? g_wqkvh : g_wouth;

  const int crow = tid >> 1;
  const int cc0 = (tid & 1) << 1;
  const unsigned so0 = swz(crow, cc0);
  const unsigned so1 = swz(crow, cc0 + 1);
  // mode 0: gather x rows at original position s(m); mode 1: linear compacted
  const int arow = (mode == 0) ? cmap(bm + crow) : (bm + crow);
  const __half* ga = A + (size_t)arow * E + cc0 * 8;
  const __half* gb = B + (size_t)(bn + crow) * E + cc0 * 8;

  auto issue = [&](int kt) {
    unsigned sa = smb + (unsigned)((kt % GSTAGES) * 16384);
    unsigned sb = sa + 8192u;
    const __half* pa = ga + kt * 32;
    const __half* pb = gb + kt * 32;
    cp16(sa + so0, pa);
    cp16(sa + so1, pa + 8);
    cp16(sb + so0, pb);
    cp16(sb + so1, pb + 8);
    asm volatile("cp.async.commit_group;");
  };

  float acc[4][4][4];
#pragma unroll
  for (int i = 0; i < 4; i++)
#pragma unroll
    for (int j = 0; j < 4; j++)
#pragma unroll
      for (int r = 0; r < 4; r++) acc[i][j][r] = 0.f;

  const int NK = E / 32;   // 32
  issue(0);
  issue(1);

  for (int kt = 0; kt < NK; kt++) {
    if (kt < NK - 1) asm volatile("cp.async.wait_group 1;");
    else             asm volatile("cp.async.wait_group 0;");
    __syncthreads();
    if (kt + 2 < NK) issue(kt + 2);

    unsigned sa = smb + (unsigned)((kt % GSTAGES) * 16384);
    unsigned sb = sa + 8192u;
#pragma unroll
    for (int ks = 0; ks < 2; ks++) {
      unsigned af[4][4];
      const int ccA = ks * 2 + (lgrp >> 1);
#pragma unroll
      for (int ma = 0; ma < 4; ma++) {
        int row = wm * 64 + ma * 16 + ((lgrp & 1) << 3) + lane7;
        ldsm4(af[ma][0], af[ma][1], af[ma][2], af[ma][3], sa + swz(row, ccA));
      }
      unsigned bf[4][2];
      const int ccB = ks * 2 + (lgrp & 1);
#pragma unroll
      for (int nb = 0; nb < 2; nb++) {
        int row = wn * 32 + nb * 16 + ((lgrp >> 1) << 3) + lane7;
        unsigned r0, r1, r2, r3;
        ldsm4(r0, r1, r2, r3, sb + swz(row, ccB));
        bf[nb * 2][0] = r0;     bf[nb * 2][1] = r1;
        bf[nb * 2 + 1][0] = r2; bf[nb * 2 + 1][1] = r3;
      }
#pragma unroll
      for (int na = 0; na < 4; na++)
#pragma unroll
        for (int ma = 0; ma < 4; ma++)
          mma16(acc[ma][na], af[ma], bf[na][0], bf[na][1]);
    }
  }

  const int r = lane >> 2;
  const int cq = (lane & 3) << 1;
  if (mode == 0) {
#pragma unroll
    for (int ma = 0; ma < 4; ma++) {
      int row = bm + wm * 64 + ma * 16 + r;       // compacted index
      int s0 = cmap(row);
      int s1 = cmap(row + 8);
#pragma unroll
      for (int na = 0; na < 4; na++) {
        int col = bn + wn * 32 + na * 8 + cq;
        int comp = col >> 10;
        int hh = (col & 1023) >> 6;
        int dd = col & 63;
        __half* base = (comp == 0) ? g_Qh : (comp == 1) ? g_Kh : g_Vh;
        float sc = (comp == 0) ? 0.125f * 1.44269504f : 1.0f;
        float2 b2 = *(const float2*)&bias[col];
        unsigned v0 = packh2((acc[ma][na][0] + b2.x) * sc,
                             (acc[ma][na][1] + b2.y) * sc);
        unsigned v1 = packh2((acc[ma][na][2] + b2.x) * sc,
                             (acc[ma][na][3] + b2.y) * sc);
        *(unsigned*)(base + (size_t)hh * S * D + (size_t)s0 * 64 + dd) = v0;
        *(unsigned*)(base + (size_t)hh * S * D + (size_t)s1 * 64 + dd) = v1;
      }
    }
  } else {
    const float third = 1.0f / 3.0f;
#pragma unroll
    for (int ma = 0; ma < 4; ma++) {
      int row = bm + wm * 64 + ma * 16 + r;       // compacted index
      int s0 = cmap(row);
      int s1 = cmap(row + 8);
#pragma unroll
      for (int na = 0; na < 4; na++) {
        int col = bn + wn * 32 + na * 8 + cq;
        float2 b2 = *(const float2*)&bias[col];
        float2 v0, v1;
        v0.x = fmaf(acc[ma][na][0], third, b2.x);
        v0.y = fmaf(acc[ma][na][1], third, b2.y);
        v1.x = fmaf(acc[ma][na][2], third, b2.x);
        v1.y = fmaf(acc[ma][na][3], third, b2.y);
        *(float2*)&Cgm[(size_t)s0 * E + col] = v0;
        *(float2*)&Cgm[(size_t)s1 * E + col] = v1;
      }
    }
  }
}

// ---------------------------------------------------------------------------
// FA2 flash attention v5 (R12, verbatim): ones-column l, vote-uniform rescale
// skip, long-first CTA ordering (seg1 first). Reads Q/K/V at ORIGINAL rows.
// ---------------------------------------------------------------------------
__global__ __launch_bounds__(256, 2) void flash_fp16_v5() {
  __shared__ __align__(1024) unsigned char smem_raw[32768];
  const unsigned smb = su32(smem_raw);
  const int tid = threadIdx.x, lane = tid & 31, w = tid >> 5;
  const int lane7 = lane & 7, lgrp = lane >> 3;

  const int id = blockIdx.x;
  const int h = id & 15, qb = id >> 4;
  int qblock, n, dil, seg;
  if (qb < 32)      { seg = 1; qblock = qb;      n = 4096; dil = 2; }  // long first
  else if (qb < 48) { seg = 0; qblock = qb - 32; n = 2048; dil = 1; }
  else              { seg = 2; qblock = qb - 48; n = 2048; dil = 4; }

  const __half* Qh = g_Qh + (size_t)h * S * D;
  const __half* Kh = g_Kh + (size_t)h * S * D;
  const __half* Vh = g_Vh + (size_t)h * S * D;

  const int r0 = qblock * 128 + w * 16 + (lane >> 2);
  const int r1 = r0 + 8;
  unsigned qf[4][4];
  {
    const unsigned* q0u = (const unsigned*)(Qh + (size_t)r0 * dil * 64);
    const unsigned* q1u = (const unsigned*)(Qh + (size_t)r1 * dil * 64);
#pragma unroll
    for (int t = 0; t < 4; t++) {
      int x = t * 8 + (lane & 3);
      qf[t][0] = q0u[x];     qf[t][1] = q1u[x];
      qf[t][2] = q0u[x + 4]; qf[t][3] = q1u[x + 4];
    }
  }

  float oacc[8][4];
#pragma unroll
  for (int b = 0; b < 8; b++)
#pragma unroll
    for (int rr = 0; rr < 4; rr++) oacc[b][rr] = 0.f;
  float lacc[4] = {0.f, 0.f, 0.f, 0.f};   // l in mma accumulator (ones column)
  float m0 = -1e30f, m1 = -1e30f;

  const int krow = tid >> 2;
  const int kc0 = (tid & 3) * 2;
  const unsigned dOff0 = krow * 128 + (((kc0)     ^ (krow & 7)) << 4);
  const unsigned dOff1 = krow * 128 + (((kc0 + 1) ^ (krow & 7)) << 4);

  const unsigned rowS = (unsigned)(((lgrp >> 1) * 8 + lane7) * 128);
  unsigned cS[4];
#pragma unroll
  for (int t = 0; t < 4; t++)
    cS[t] = (unsigned)((((t * 2 + (lgrp & 1)) ^ lane7)) << 4);
  const unsigned rowV = (unsigned)((lgrp * 8 + lane7) * 128);

  const int ntiles = n >> 6;
  auto issue = [&](int kt) {
    int base = kt * 64;
    const char* ks = (const char*)(Kh + (size_t)(base + krow) * dil * 64) + kc0 * 16;
    const char* vs = (const char*)(Vh + (size_t)(base + krow) * dil * 64) + kc0 * 16;
    unsigned kb = smb + (unsigned)((kt & 1) * 8192);
    unsigned vb = smb + 16384u + (unsigned)((kt & 1) * 8192);
    cp16(kb + dOff0, ks);
    cp16(kb + dOff1, ks + 16);
    cp16(vb + dOff0, vs);
    cp16(vb + dOff1, vs + 16);
    asm volatile("cp.async.commit_group;");
  };

  const unsigned ONESH2 = 0x3C003C00u;   // half2(1.0, 1.0)

  issue(0);
  for (int kt = 0; kt < ntiles; kt++) {
    if (kt + 1 < ntiles) {
      issue(kt + 1);
      asm volatile("cp.async.wait_group 1;");
    } else {
      asm volatile("cp.async.wait_group 0;");
    }
    __syncthreads();

    const unsigned kbuf = smb + (unsigned)((kt & 1) * 8192);
    const unsigned vbuf = smb + 16384u + (unsigned)((kt & 1) * 8192);

    // S = Q K^T
    float sacc[8][4];
#pragma unroll
    for (int b = 0; b < 8; b++)
#pragma unroll
      for (int rr = 0; rr < 4; rr++) sacc[b][rr] = 0.f;
#pragma unroll
    for (int b2 = 0; b2 < 4; b2++) {
      unsigned basea = kbuf + (unsigned)(b2 * 2048) + rowS;
#pragma unroll
      for (int t = 0; t < 4; t++) {
        unsigned x0, x1, x2, x3;
        ldsm4(x0, x1, x2, x3, basea + cS[t]);
        mma16(sacc[2 * b2], qf[t], x0, x1);
        mma16(sacc[2 * b2 + 1], qf[t], x2, x3);
      }
    }

    // online softmax (log2 domain): max + P fragments only
    float mx0 = -1e30f, mx1 = -1e30f;
#pragma unroll
    for (int b = 0; b < 8; b++) {
      mx0 = fmaxf(mx0, fmaxf(sacc[b][0], sacc[b][1]));
      mx1 = fmaxf(mx1, fmaxf(sacc[b][2], sacc[b][3]));
    }
    mx0 = fmaxf(mx0, __shfl_xor_sync(0xffffffff, mx0, 1));
    mx0 = fmaxf(mx0, __shfl_xor_sync(0xffffffff, mx0, 2));
    mx1 = fmaxf(mx1, __shfl_xor_sync(0xffffffff, mx1, 1));
    mx1 = fmaxf(mx1, __shfl_xor_sync(0xffffffff, mx1, 2));
    float nm0 = fmaxf(m0, mx0), nm1 = fmaxf(m1, mx1);
    float al0 = ex2f(m0 - nm0), al1 = ex2f(m1 - nm1);
    m0 = nm0; m1 = nm1;

    unsigned pf[4][4];
#pragma unroll
    for (int b = 0; b < 8; b++) {
      pf[b >> 1][(b & 1) * 2] =
          h2ex2(packh2(sacc[b][0] - nm0, sacc[b][1] - nm0));
      pf[b >> 1][(b & 1) * 2 + 1] =
          h2ex2(packh2(sacc[b][2] - nm1, sacc[b][3] - nm1));
    }

    // vote-uniform rescale skip (no intra-warp divergence)
    if (__any_sync(0xffffffff, (al0 != 1.0f) || (al1 != 1.0f))) {
#pragma unroll
      for (int b = 0; b < 8; b++) {
        oacc[b][0] *= al0; oacc[b][1] *= al0;
        oacc[b][2] *= al1; oacc[b][3] *= al1;
      }
      lacc[0] *= al0; lacc[1] *= al0;
      lacc[2] *= al1; lacc[3] *= al1;
    }

    // l += P * ones  (all 8 output columns equal -> every lane has its row sum)
#pragma unroll
    for (int t = 0; t < 4; t++) mma16(lacc, pf[t], ONESH2, ONESH2);

    // O += P V
#pragma unroll
    for (int b = 0; b < 8; b++) {
      unsigned cv = (unsigned)(((b ^ lane7)) << 4);
      unsigned x0, x1, x2, x3, y0, y1, y2, y3;
      ldsm4t(x0, x1, x2, x3, vbuf + rowV + cv);
      ldsm4t(y0, y1, y2, y3, vbuf + rowV + 32u * 128u + cv);
      mma16(oacc[b], pf[0], x0, x1);
      mma16(oacc[b], pf[1], x2, x3);
      mma16(oacc[b], pf[2], y0, y1);
      mma16(oacc[b], pf[3], y2, y3);
    }
    __syncthreads();
  }

  const float inv0 = 1.0f / lacc[0], inv1 = 1.0f / lacc[2];
  float* base = g_A[seg];
  float* a0 = base + (size_t)r0 * dil * E + h * 64;
  float* a1 = base + (size_t)r1 * dil * E + h * 64;
#pragma unroll
  for (int b = 0; b < 8; b++) {
    int dd = b * 8 + ((lane & 3) << 1);
    *(float2*)&a0[dd] = make_float2(oacc[b][0] * inv0, oacc[b][1] * inv0);
    *(float2*)&a1[dd] = make_float2(oacc[b][2] * inv1, oacc[b][3] * inv1);
  }
}

// ---------------------------------------------------------------------------
extern "C" void kernel_launch(void* const* d_in, const int* in_sizes, int n_in,
                              void* d_out, int out_size) {
  const float* x     = (const float*)d_in[0];  // [S, E]
  const float* w_qkv = (const float*)d_in[1];  // [3E, E]
  const float* b_qkv = (const float*)d_in[2];  // [3E]
  const float* w_out = (const float*)d_in[3];  // [E, E]
  const float* b_out = (const float*)d_in[4];  // [E]
  float* out = (float*)d_out;                  // [S, E]

  // fused fp32 -> fp16 prepass (one launch)
  cvt_all_kernel<<<(N4_X + N4_WQ + N4_WO) / 256, 256>>>(x, w_qkv, w_out);

  // QKV projection over COMPACTED rows (M=5120), scatter to original positions
  gemm_v2<<<dim3(E3 / 128, MC / 128), 256>>>(b_qkv, nullptr, 0);

  // fused flash: 64 q-blocks (32 seg1 + 16 seg0 + 16 seg2) x 16 heads
  flash_fp16_v5<<<64 * 16, 256>>>();

  // bias-only rows (odd s >= 2048): out = b_out
  bias_fill_kernel<<<(3072 * 256) / 256, 256>>>(b_out, out);

  // compacted predicated sum -> fp16 A operand (M = 5120)
  sum_a_compact_kernel<<<(MC * E / 4) / 256, 256>>>();

  // output projection over compacted rows, epilogue scatters to s(m)
  gemm_v2<<<dim3(E / 128, MC / 128), 256>>>(b_out, out, 1);
}

// round 17
// speedup vs baseline: 1.3692x; 1.0088x over previous
#include <cuda_runtime.h>
#include <cuda_fp16.h>

#define S 8192
#define E 1024
#define H 16
#define D 64
#define E3 3072
#define MC 5120   // compacted M: 2048 + 3072 covered upper rows (even s >= 2048)

// Scratch (allocation-free rule: __device__ globals, referenced ONLY in device code)
__device__ __align__(128) __half g_Qh[H * S * D];   // pre-scaled by log2e/sqrt(D)
__device__ __align__(128) __half g_Kh[H * S * D];
__device__ __align__(128) __half g_Vh[H * S * D];
__device__ __align__(128) float  g_A[3][S * E];     // per-segment attention out (fp32)
__device__ __align__(128) __half g_xh[S * E];       // fp16 x, COMPACTED rows (MC used)
__device__ __align__(128) __half g_wqkvh[E3 * E];   // fp16 copy of w_qkv
__device__ __align__(128) __half g_wouth[E * E];    // fp16 copy of w_out
__device__ __align__(128) __half g_Ah[S * E];       // fp16 COMPACTED attention out

// ---------------------------------------------------------------------------
// helpers
// ---------------------------------------------------------------------------
__device__ __forceinline__ unsigned packh2(float lo, float hi) {
  __half2 h = __float22half2_rn(make_float2(lo, hi));
  return *reinterpret_cast<unsigned*>(&h);
}
__device__ __forceinline__ float ex2f(float x) {
  float y; asm("ex2.approx.ftz.f32 %0, %1;" : "=f"(y) : "f"(x)); return y;
}
__device__ __forceinline__ unsigned h2ex2(unsigned x) {
  unsigned y; asm("ex2.approx.f16x2 %0, %1;" : "=r"(y) : "r"(x)); return y;
}
__device__ __forceinline__ unsigned su32(const void* p) {
  unsigned a;
  asm("{.reg .u64 t; cvta.to.shared.u64 t, %1; cvt.u32.u64 %0, t;}"
      : "=r"(a) : "l"(p));
  return a;
}
__device__ __forceinline__ void cp16(unsigned d, const void* s) {
  asm volatile("cp.async.cg.shared.global [%0], [%1], 16;" :: "r"(d), "l"(s));
}
__device__ __forceinline__ void ldsm4(unsigned& r0, unsigned& r1, unsigned& r2,
                                      unsigned& r3, unsigned a) {
  asm volatile("ldmatrix.sync.aligned.m8n8.x4.shared.b16 {%0,%1,%2,%3},[%4];"
               : "=r"(r0), "=r"(r1), "=r"(r2), "=r"(r3) : "r"(a));
}
__device__ __forceinline__ void ldsm4t(unsigned& r0, unsigned& r1, unsigned& r2,
                                       unsigned& r3, unsigned a) {
  asm volatile("ldmatrix.sync.aligned.m8n8.x4.trans.shared.b16 {%0,%1,%2,%3},[%4];"
               : "=r"(r0), "=r"(r1), "=r"(r2), "=r"(r3) : "r"(a));
}
__device__ __forceinline__ void mma16(float* d, const unsigned* a, unsigned b0,
                                      unsigned b1) {
  asm volatile(
      "mma.sync.aligned.m16n8k16.row.col.f32.f16.f16.f32 "
      "{%0,%1,%2,%3},{%4,%5,%6,%7},{%8,%9},{%0,%1,%2,%3};"
      : "+f"(d[0]), "+f"(d[1]), "+f"(d[2]), "+f"(d[3])
      : "r"(a[0]), "r"(a[1]), "r"(a[2]), "r"(a[3]), "r"(b0), "r"(b1));
}
// smem swizzle for gemm: 128B macro-rows (2 logical 64B rows)
__device__ __forceinline__ unsigned swz(int row, int c) {
  return (unsigned)((row >> 1) * 128 +
                    (((((row & 1) << 2) | c) ^ ((row >> 1) & 7)) << 4));
}
// compacted index -> original sequence position
__device__ __forceinline__ int cmap(int m) {
  return (m < 2048) ? m : 2048 + ((m - 2048) << 1);
}

// ---------------------------------------------------------------------------
// Fused fp32 -> fp16 conversion prepass. x is converted ONLY for the MC
// covered rows, written COMPACTED into g_xh (gather from original s(m)).
// ---------------------------------------------------------------------------
#define N4_XC  (MC * E / 4)       // 1310720 (compacted x)
#define N4_WQ  (E3 * E / 4)       // 786432
#define N4_WO  (E * E / 4)        // 262144
__global__ void cvt_all_kernel(const float* __restrict__ x,
                               const float* __restrict__ wqkv,
                               const float* __restrict__ wout) {
  int i = blockIdx.x * blockDim.x + threadIdx.x;
  const float4* src;
  uint2* dst;
  if (i < N4_XC) {
    int m = i >> 8;
    int s = cmap(m);
    src = (const float4*)x + ((size_t)s * 256 + (i & 255));
    dst = (uint2*)g_xh + i;
  } else if (i < N4_XC + N4_WQ) {
    src = (const float4*)wqkv + (i - N4_XC);
    dst = (uint2*)g_wqkvh + (i - N4_XC);
  } else {
    src = (const float4*)wout + (i - N4_XC - N4_WQ);
    dst = (uint2*)g_wouth + (i - N4_XC - N4_WQ);
  }
  float4 v = *src;
  *dst = make_uint2(packh2(v.x, v.y), packh2(v.z, v.w));
}

// ---------------------------------------------------------------------------
// Fused post-attention pass (one launch):
//  part 1 (i < MC*E/4): compacted predicated sum -> g_Ah
//  part 2 (rest):       bias-only rows (odd s >= 2048) -> out = b_out
// ---------------------------------------------------------------------------
#define N4_SUM (MC * E / 4)        // 1310720
#define N4_BF  (3072 * 256)        // 786432
__global__ void post_kernel(const float* __restrict__ bias,
                            float* __restrict__ out) {
  int i = blockIdx.x * blockDim.x + threadIdx.x;
  if (i < N4_SUM) {
    int m = i >> 8;
    int s = cmap(m);
    size_t off = (size_t)s * 256 + (i & 255);
    float4 a = make_float4(0.f, 0.f, 0.f, 0.f);
    if (s < 2048) {
      float4 v = ((const float4*)g_A[0])[off];
      a.x += v.x; a.y += v.y; a.z += v.z; a.w += v.w;
    }
    if (!(s & 1)) {
      float4 v = ((const float4*)g_A[1])[off];
      a.x += v.x; a.y += v.y; a.z += v.z; a.w += v.w;
    }
    if (!(s & 3)) {
      float4 v = ((const float4*)g_A[2])[off];
      a.x += v.x; a.y += v.y; a.z += v.z; a.w += v.w;
    }
    ((uint2*)g_Ah)[i] = make_uint2(packh2(a.x, a.y), packh2(a.z, a.w));
  } else {
    int j = i - N4_SUM;            // over 3072*256
    int row = j >> 8;
    int e4 = j & 255;
    int s = 2049 + (row << 1);
    ((float4*)out)[(size_t)s * 256 + e4] = ((const float4*)bias)[e4];
  }
}

// ---------------------------------------------------------------------------
// fp16 GEMM v2 (FROZEN mainloop): 128x128x32 tile, 256 threads, 3-stage
// cp.async + ldmatrix. Both modes over COMPACTED M = 5120, linear A reads:
// mode 0: A = g_xh (compacted), scatter Q/K/V to ORIGINAL rows s(m).
// mode 1: A = g_Ah (compacted), out = acc/3 + bias scattered to s(m).
// ---------------------------------------------------------------------------
#define GSTAGES 3
__global__ __launch_bounds__(256, 2) void gemm_v2(
    const float* __restrict__ bias, float* __restrict__ Cgm, int mode) {
  __shared__ __align__(1024) unsigned char smem_raw[GSTAGES * 16384];
  const unsigned smb = su32(smem_raw);
  const int tid = threadIdx.x, lane = tid & 31, w = tid >> 5;
  const int wm = w & 1, wn = w >> 1;
  const int lane7 = lane & 7, lgrp = lane >> 3;
  const int bm = blockIdx.y * 128, bn = blockIdx.x * 128;

  const __half* A = (mode == 0) ? g_xh : g_Ah;
  const __half* B = (mode == 0) ? g_wqkvh : g_wouth;

  const int crow = tid >> 1;
  const int cc0 = (tid & 1) << 1;
  const unsigned so0 = swz(crow, cc0);
  const unsigned so1 = swz(crow, cc0 + 1);
  const __half* ga = A + (size_t)(bm + crow) * E + cc0 * 8;
  const __half* gb = B + (size_t)(bn + crow) * E + cc0 * 8;

  auto issue = [&](int kt) {
    unsigned sa = smb + (unsigned)((kt % GSTAGES) * 16384);
    unsigned sb = sa + 8192u;
    const __half* pa = ga + kt * 32;
    const __half* pb = gb + kt * 32;
    cp16(sa + so0, pa);
    cp16(sa + so1, pa + 8);
    cp16(sb + so0, pb);
    cp16(sb + so1, pb + 8);
    asm volatile("cp.async.commit_group;");
  };

  float acc[4][4][4];
#pragma unroll
  for (int i = 0; i < 4; i++)
#pragma unroll
    for (int j = 0; j < 4; j++)
#pragma unroll
      for (int r = 0; r < 4; r++) acc[i][j][r] = 0.f;

  const int NK = E / 32;   // 32
  issue(0);
  issue(1);

  for (int kt = 0; kt < NK; kt++) {
    if (kt < NK - 1) asm volatile("cp.async.wait_group 1;");
    else             asm volatile("cp.async.wait_group 0;");
    __syncthreads();
    if (kt + 2 < NK) issue(kt + 2);

    unsigned sa = smb + (unsigned)((kt % GSTAGES) * 16384);
    unsigned sb = sa + 8192u;
#pragma unroll
    for (int ks = 0; ks < 2; ks++) {
      unsigned af[4][4];
      const int ccA = ks * 2 + (lgrp >> 1);
#pragma unroll
      for (int ma = 0; ma < 4; ma++) {
        int row = wm * 64 + ma * 16 + ((lgrp & 1) << 3) + lane7;
        ldsm4(af[ma][0], af[ma][1], af[ma][2], af[ma][3], sa + swz(row, ccA));
      }
      unsigned bf[4][2];
      const int ccB = ks * 2 + (lgrp & 1);
#pragma unroll
      for (int nb = 0; nb < 2; nb++) {
        int row = wn * 32 + nb * 16 + ((lgrp >> 1) << 3) + lane7;
        unsigned r0, r1, r2, r3;
        ldsm4(r0, r1, r2, r3, sb + swz(row, ccB));
        bf[nb * 2][0] = r0;     bf[nb * 2][1] = r1;
        bf[nb * 2 + 1][0] = r2; bf[nb * 2 + 1][1] = r3;
      }
#pragma unroll
      for (int na = 0; na < 4; na++)
#pragma unroll
        for (int ma = 0; ma < 4; ma++)
          mma16(acc[ma][na], af[ma], bf[na][0], bf[na][1]);
    }
  }

  const int r = lane >> 2;
  const int cq = (lane & 3) << 1;
  if (mode == 0) {
#pragma unroll
    for (int ma = 0; ma < 4; ma++) {
      int row = bm + wm * 64 + ma * 16 + r;       // compacted index
      int s0 = cmap(row);
      int s1 = cmap(row + 8);
#pragma unroll
      for (int na = 0; na < 4; na++) {
        int col = bn + wn * 32 + na * 8 + cq;
        int comp = col >> 10;
        int hh = (col & 1023) >> 6;
        int dd = col & 63;
        __half* base = (comp == 0) ? g_Qh : (comp == 1) ? g_Kh : g_Vh;
        float sc = (comp == 0) ? 0.125f * 1.44269504f : 1.0f;
        float2 b2 = *(const float2*)&bias[col];
        unsigned v0 = packh2((acc[ma][na][0] + b2.x) * sc,
                             (acc[ma][na][1] + b2.y) * sc);
        unsigned v1 = packh2((acc[ma][na][2] + b2.x) * sc,
                             (acc[ma][na][3] + b2.y) * sc);
        *(unsigned*)(base + (size_t)hh * S * D + (size_t)s0 * 64 + dd) = v0;
        *(unsigned*)(base + (size_t)hh * S * D + (size_t)s1 * 64 + dd) = v1;
      }
    }
  } else {
    const float third = 1.0f / 3.0f;
#pragma unroll
    for (int ma = 0; ma < 4; ma++) {
      int row = bm + wm * 64 + ma * 16 + r;       // compacted index
      int s0 = cmap(row);
      int s1 = cmap(row + 8);
#pragma unroll
      for (int na = 0; na < 4; na++) {
        int col = bn + wn * 32 + na * 8 + cq;
        float2 b2 = *(const float2*)&bias[col];
        float2 v0, v1;
        v0.x = fmaf(acc[ma][na][0], third, b2.x);
        v0.y = fmaf(acc[ma][na][1], third, b2.y);
        v1.x = fmaf(acc[ma][na][2], third, b2.x);
        v1.y = fmaf(acc[ma][na][3], third, b2.y);
        *(float2*)&Cgm[(size_t)s0 * E + col] = v0;
        *(float2*)&Cgm[(size_t)s1 * E + col] = v1;
      }
    }
  }
}

// ---------------------------------------------------------------------------
// FA2 flash attention v5 (R12, verbatim): ones-column l, vote-uniform rescale
// skip, long-first CTA ordering (seg1 first). Reads Q/K/V at ORIGINAL rows.
// ---------------------------------------------------------------------------
__global__ __launch_bounds__(256, 2) void flash_fp16_v5() {
  __shared__ __align__(1024) unsigned char smem_raw[32768];
  const unsigned smb = su32(smem_raw);
  const int tid = threadIdx.x, lane = tid & 31, w = tid >> 5;
  const int lane7 = lane & 7, lgrp = lane >> 3;

  const int id = blockIdx.x;
  const int h = id & 15, qb = id >> 4;
  int qblock, n, dil, seg;
  if (qb < 32)      { seg = 1; qblock = qb;      n = 4096; dil = 2; }  // long first
  else if (qb < 48) { seg = 0; qblock = qb - 32; n = 2048; dil = 1; }
  else              { seg = 2; qblock = qb - 48; n = 2048; dil = 4; }

  const __half* Qh = g_Qh + (size_t)h * S * D;
  const __half* Kh = g_Kh + (size_t)h * S * D;
  const __half* Vh = g_Vh + (size_t)h * S * D;

  const int r0 = qblock * 128 + w * 16 + (lane >> 2);
  const int r1 = r0 + 8;
  unsigned qf[4][4];
  {
    const unsigned* q0u = (const unsigned*)(Qh + (size_t)r0 * dil * 64);
    const unsigned* q1u = (const unsigned*)(Qh + (size_t)r1 * dil * 64);
#pragma unroll
    for (int t = 0; t < 4; t++) {
      int x = t * 8 + (lane & 3);
      qf[t][0] = q0u[x];     qf[t][1] = q1u[x];
      qf[t][2] = q0u[x + 4]; qf[t][3] = q1u[x + 4];
    }
  }

  float oacc[8][4];
#pragma unroll
  for (int b = 0; b < 8; b++)
#pragma unroll
    for (int rr = 0; rr < 4; rr++) oacc[b][rr] = 0.f;
  float lacc[4] = {0.f, 0.f, 0.f, 0.f};   // l in mma accumulator (ones column)
  float m0 = -1e30f, m1 = -1e30f;

  const int krow = tid >> 2;
  const int kc0 = (tid & 3) * 2;
  const unsigned dOff0 = krow * 128 + (((kc0)     ^ (krow & 7)) << 4);
  const unsigned dOff1 = krow * 128 + (((kc0 + 1) ^ (krow & 7)) << 4);

  const unsigned rowS = (unsigned)(((lgrp >> 1) * 8 + lane7) * 128);
  unsigned cS[4];
#pragma unroll
  for (int t = 0; t < 4; t++)
    cS[t] = (unsigned)((((t * 2 + (lgrp & 1)) ^ lane7)) << 4);
  const unsigned rowV = (unsigned)((lgrp * 8 + lane7) * 128);

  const int ntiles = n >> 6;
  auto issue = [&](int kt) {
    int base = kt * 64;
    const char* ks = (const char*)(Kh + (size_t)(base + krow) * dil * 64) + kc0 * 16;
    const char* vs = (const char*)(Vh + (size_t)(base + krow) * dil * 64) + kc0 * 16;
    unsigned kb = smb + (unsigned)((kt & 1) * 8192);
    unsigned vb = smb + 16384u + (unsigned)((kt & 1) * 8192);
    cp16(kb + dOff0, ks);
    cp16(kb + dOff1, ks + 16);
    cp16(vb + dOff0, vs);
    cp16(vb + dOff1, vs + 16);
    asm volatile("cp.async.commit_group;");
  };

  const unsigned ONESH2 = 0x3C003C00u;   // half2(1.0, 1.0)

  issue(0);
  for (int kt = 0; kt < ntiles; kt++) {
    if (kt + 1 < ntiles) {
      issue(kt + 1);
      asm volatile("cp.async.wait_group 1;");
    } else {
      asm volatile("cp.async.wait_group 0;");
    }
    __syncthreads();

    const unsigned kbuf = smb + (unsigned)((kt & 1) * 8192);
    const unsigned vbuf = smb + 16384u + (unsigned)((kt & 1) * 8192);

    // S = Q K^T
    float sacc[8][4];
#pragma unroll
    for (int b = 0; b < 8; b++)
#pragma unroll
      for (int rr = 0; rr < 4; rr++) sacc[b][rr] = 0.f;
#pragma unroll
    for (int b2 = 0; b2 < 4; b2++) {
      unsigned basea = kbuf + (unsigned)(b2 * 2048) + rowS;
#pragma unroll
      for (int t = 0; t < 4; t++) {
        unsigned x0, x1, x2, x3;
        ldsm4(x0, x1, x2, x3, basea + cS[t]);
        mma16(sacc[2 * b2], qf[t], x0, x1);
        mma16(sacc[2 * b2 + 1], qf[t], x2, x3);
      }
    }

    // online softmax (log2 domain): max + P fragments only
    float mx0 = -1e30f, mx1 = -1e30f;
#pragma unroll
    for (int b = 0; b < 8; b++) {
      mx0 = fmaxf(mx0, fmaxf(sacc[b][0], sacc[b][1]));
      mx1 = fmaxf(mx1, fmaxf(sacc[b][2], sacc[b][3]));
    }
    mx0 = fmaxf(mx0, __shfl_xor_sync(0xffffffff, mx0, 1));
    mx0 = fmaxf(mx0, __shfl_xor_sync(0xffffffff, mx0, 2));
    mx1 = fmaxf(mx1, __shfl_xor_sync(0xffffffff, mx1, 1));
    mx1 = fmaxf(mx1, __shfl_xor_sync(0xffffffff, mx1, 2));
    float nm0 = fmaxf(m0, mx0), nm1 = fmaxf(m1, mx1);
    float al0 = ex2f(m0 - nm0), al1 = ex2f(m1 - nm1);
    m0 = nm0; m1 = nm1;

    unsigned pf[4][4];
#pragma unroll
    for (int b = 0; b < 8; b++) {
      pf[b >> 1][(b & 1) * 2] =
          h2ex2(packh2(sacc[b][0] - nm0, sacc[b][1] - nm0));
      pf[b >> 1][(b & 1) * 2 + 1] =
          h2ex2(packh2(sacc[b][2] - nm1, sacc[b][3] - nm1));
    }

    // vote-uniform rescale skip (no intra-warp divergence)
    if (__any_sync(0xffffffff, (al0 != 1.0f) || (al1 != 1.0f))) {
#pragma unroll
      for (int b = 0; b < 8; b++) {
        oacc[b][0] *= al0; oacc[b][1] *= al0;
        oacc[b][2] *= al1; oacc[b][3] *= al1;
      }
      lacc[0] *= al0; lacc[1] *= al0;
      lacc[2] *= al1; lacc[3] *= al1;
    }

    // l += P * ones  (all 8 output columns equal -> every lane has its row sum)
#pragma unroll
    for (int t = 0; t < 4; t++) mma16(lacc, pf[t], ONESH2, ONESH2);

    // O += P V
#pragma unroll
    for (int b = 0; b < 8; b++) {
      unsigned cv = (unsigned)(((b ^ lane7)) << 4);
      unsigned x0, x1, x2, x3, y0, y1, y2, y3;
      ldsm4t(x0, x1, x2, x3, vbuf + rowV + cv);
      ldsm4t(y0, y1, y2, y3, vbuf + rowV + 32u * 128u + cv);
      mma16(oacc[b], pf[0], x0, x1);
      mma16(oacc[b], pf[1], x2, x3);
      mma16(oacc[b], pf[2], y0, y1);
      mma16(oacc[b], pf[3], y2, y3);
    }
    __syncthreads();
  }

  const float inv0 = 1.0f / lacc[0], inv1 = 1.0f / lacc[2];
  float* base = g_A[seg];
  float* a0 = base + (size_t)r0 * dil * E + h * 64;
  float* a1 = base + (size_t)r1 * dil * E + h * 64;
#pragma unroll
  for (int b = 0; b < 8; b++) {
    int dd = b * 8 + ((lane & 3) << 1);
    *(float2*)&a0[dd] = make_float2(oacc[b][0] * inv0, oacc[b][1] * inv0);
    *(float2*)&a1[dd] = make_float2(oacc[b][2] * inv1, oacc[b][3] * inv1);
  }
}

// ---------------------------------------------------------------------------
extern "C" void kernel_launch(void* const* d_in, const int* in_sizes, int n_in,
                              void* d_out, int out_size) {
  const float* x     = (const float*)d_in[0];  // [S, E]
  const float* w_qkv = (const float*)d_in[1];  // [3E, E]
  const float* b_qkv = (const float*)d_in[2];  // [3E]
  const float* w_out = (const float*)d_in[3];  // [E, E]
  const float* b_out = (const float*)d_in[4];  // [E]
  float* out = (float*)d_out;                  // [S, E]

  // fused fp32 -> fp16 prepass (x compacted to covered rows; one launch)
  cvt_all_kernel<<<(N4_XC + N4_WQ + N4_WO) / 256, 256>>>(x, w_qkv, w_out);

  // QKV projection over COMPACTED rows (M=5120), scatter to original positions
  gemm_v2<<<dim3(E3 / 128, MC / 128), 256>>>(b_qkv, nullptr, 0);

  // fused flash: 64 q-blocks (32 seg1 + 16 seg0 + 16 seg2) x 16 heads
  flash_fp16_v5<<<64 * 16, 256>>>();

  // fused post pass: compacted predicated sum + bias-only rows (one launch)
  post_kernel<<<(N4_SUM + N4_BF) / 256, 256>>>(b_out, out);

  // output projection over compacted rows, epilogue scatters to s(m)
  gemm_v2<<<dim3(E / 128, MC / 128), 256>>>(b_out, out, 1);
}